// round 10
// baseline (speedup 1.0000x reference)
#include <cuda_runtime.h>
#include <cuda_bf16.h>
#include <cuda_fp16.h>
#include <math.h>
#include <stdint.h>

// ---------------- problem constants ----------------
#define BSZ   512
#define LSZ   160
#define DDIM  350
#define DP    352     // padded D
#define DPW   176     // DP/2 packed words
#define NCH   600
#define NPAD  640
#define CWP   20      // smem word pitch (16 + 4 pad)
#define ZPITCH 132    // conv Z smem pitch

// ---------------- device scratch ----------------
__device__ unsigned g_lvh [(size_t)BSZ * LSZ * DPW];   // l_vec split hi (bf16x2)
__device__ unsigned g_lvl [(size_t)BSZ * LSZ * DPW];   // l_vec split lo
__device__ unsigned g_rvh [(size_t)BSZ * LSZ * DPW];
__device__ unsigned g_rvl [(size_t)BSZ * LSZ * DPW];
__device__ float    g_att [(size_t)BSZ * LSZ * LSZ];
__device__ float    g_attT[(size_t)BSZ * LSZ * LSZ];
__device__ unsigned g_lcx [(size_t)BSZ * LSZ * DPW];   // l_c as half2
__device__ unsigned g_rcx [(size_t)BSZ * LSZ * DPW];   // r_c as half2
__device__ unsigned g_wallh[(size_t)NPAD * DPW];       // wall fp16 hi (half2)
__device__ unsigned g_walll[(size_t)NPAD * DPW];       // wall fp16 lo (half2)
__device__ float    g_feats[(size_t)BSZ * NCH];

// ---------------- split helpers ----------------
__device__ __forceinline__ void split2(float a, float b, unsigned& hi, unsigned& lo) {
    __nv_bfloat162 h = __floats2bfloat162_rn(a, b);
    float ra = a - __bfloat162float(h.x);
    float rb = b - __bfloat162float(h.y);
    __nv_bfloat162 l = __floats2bfloat162_rn(ra, rb);
    hi = *(unsigned*)&h;
    lo = *(unsigned*)&l;
}
__device__ __forceinline__ void split2h(float a, float b, unsigned& hi, unsigned& lo) {
    __half2 h = __floats2half2_rn(a, b);
    float ra = a - __half2float(__low2half(h));
    float rb = b - __half2float(__high2half(h));
    __half2 l = __floats2half2_rn(ra, rb);
    hi = *(unsigned*)&h;
    lo = *(unsigned*)&l;
}
__device__ __forceinline__ float2 rec2(unsigned h, unsigned l) {
    __nv_bfloat162 hb = *(__nv_bfloat162*)&h;
    __nv_bfloat162 lb = *(__nv_bfloat162*)&l;
    float2 r;
    r.x = __bfloat162float(hb.x) + __bfloat162float(lb.x);
    r.y = __bfloat162float(hb.y) + __bfloat162float(lb.y);
    return r;
}
__device__ __forceinline__ void mma16(float* c, const unsigned* a, unsigned b0, unsigned b1) {
    asm volatile(
        "mma.sync.aligned.m16n8k16.row.col.f32.bf16.bf16.f32 "
        "{%0,%1,%2,%3}, {%4,%5,%6,%7}, {%8,%9}, {%0,%1,%2,%3};"
        : "+f"(c[0]), "+f"(c[1]), "+f"(c[2]), "+f"(c[3])
        : "r"(a[0]), "r"(a[1]), "r"(a[2]), "r"(a[3]), "r"(b0), "r"(b1));
}
__device__ __forceinline__ void mma16h(float* c, const unsigned* a, unsigned b0, unsigned b1) {
    asm volatile(
        "mma.sync.aligned.m16n8k16.row.col.f32.f16.f16.f32 "
        "{%0,%1,%2,%3}, {%4,%5,%6,%7}, {%8,%9}, {%0,%1,%2,%3};"
        : "+f"(c[0]), "+f"(c[1]), "+f"(c[2]), "+f"(c[3])
        : "r"(a[0]), "r"(a[1]), "r"(a[2]), "r"(a[3]), "r"(b0), "r"(b1));
}
__device__ __forceinline__ void ldx4(unsigned* r, unsigned addr) {
    asm volatile("ldmatrix.sync.aligned.m8n8.x4.shared.b16 {%0,%1,%2,%3}, [%4];"
                 : "=r"(r[0]), "=r"(r[1]), "=r"(r[2]), "=r"(r[3]) : "r"(addr));
}
__device__ __forceinline__ void cp16(unsigned dst, const void* src, bool pred) {
    int sz = pred ? 16 : 0;
    asm volatile("cp.async.ca.shared.global [%0], [%1], 16, %2;"
                 :: "r"(dst), "l"(src), "r"(sz));
}
__device__ __forceinline__ void cpcommit() { asm volatile("cp.async.commit_group;"); }
template<int N> __device__ __forceinline__ void cpwait() {
    asm volatile("cp.async.wait_group %0;" :: "n"(N));
}

// ---------------- merged init: zero feats + build permuted fp16-split wall ------
__global__ void init_kernel(const float* __restrict__ w1,
                            const float* __restrict__ w2,
                            const float* __restrict__ w3) {
    int idx = blockIdx.x * blockDim.x + threadIdx.x;
    if (idx < BSZ * NCH) g_feats[idx] = 0.f;
    if (idx < NPAD * DPW) {
        int nn = idx / DPW, p = idx % DPW;
        int tile = nn >> 7, j = nn & 127;
        int o = tile * 20 + j / 6;
        int g = j % 6;
        bool valid = (j < 120) && (o < 100);
        float v[2];
#pragma unroll
        for (int c = 0; c < 2; c++) {
            int k = 2 * p + c;
            float x = 0.f;
            if (valid && k < DDIM) {
                if      (g == 0) x = w1[o * DDIM + k];
                else if (g <= 2) x = w2[o * (DDIM * 2) + k * 2 + (g - 1)];
                else             x = w3[o * (DDIM * 3) + k * 3 + (g - 3)];
            }
            v[c] = x;
        }
        unsigned hi, lo;
        split2h(v[0], v[1], hi, lo);
        g_wallh[idx] = hi;
        g_walll[idx] = lo;
    }
}

// ---------------- embedding gather (len-trimmed) -> pre-split bf16 hi/lo --------
__global__ void gather_kernel(const int* __restrict__ lt, const int* __restrict__ la,
                              const int* __restrict__ rt, const int* __restrict__ ra,
                              const float* __restrict__ wemb, const float* __restrict__ aemb,
                              const int* __restrict__ ll, const int* __restrict__ rl) {
    int l = blockIdx.x, b = blockIdx.y, side = blockIdx.z;
    int len = side ? rl[b] : ll[b];
    if (l >= len) return;                    // rows >= len are never read downstream
    const int* tok = side ? rt : lt;
    const int* atr = side ? ra : la;
    size_t rowo = ((size_t)(b * LSZ + l)) * DPW;
    unsigned* dstH = (side ? g_rvh : g_lvh) + rowo;
    unsigned* dstL = (side ? g_rvl : g_lvl) + rowo;
    int t = tok[l * BSZ + b];
    int a = atr[l * BSZ + b];
    const float* wr = wemb + (size_t)t * 300;
    const float* ar = aemb + (size_t)a * 50;
    int q = threadIdx.x;
    if (q < 88) {
        int d0 = q * 4;
        float v[4];
#pragma unroll
        for (int c = 0; c < 4; c++) {
            int d = d0 + c;
            float x = 0.f;
            if (d < 50) x = __ldg(ar + d);
            else if (d < DDIM) x = __ldg(wr + d - 50);
            v[c] = x;
        }
        unsigned hi, lo;
        split2(v[0], v[1], hi, lo);
        dstH[q * 2] = hi; dstL[q * 2] = lo;
        split2(v[2], v[3], hi, lo);
        dstH[q * 2 + 1] = hi; dstL[q * 2 + 1] = lo;
    }
}

// =====================================================================
// att GEMM: 64x64 tile, 4 warps (2m x 2n, 32x32 warp tiles, conv-proven
// fragment geometry), cp.async 2-stage + ldmatrix, bf16 3-term split.
// =====================================================================
#define AST_AH 0
#define AST_AL (64 * CWP)
#define AST_BH (2 * 64 * CWP)
#define AST_BL (3 * 64 * CWP)
#define AST_W  (4 * 64 * CWP)
#define NKB    11

__global__ __launch_bounds__(128) void att_gemm_kernel(const int* __restrict__ llen,
                                                       const int* __restrict__ rlen) {
    extern __shared__ unsigned asw[];
    int b  = blockIdx.z;
    int m0 = blockIdx.x * 64;
    int n0 = blockIdx.y * 64;
    if (m0 >= llen[b] || n0 >= rlen[b]) return;

    const unsigned* Avh = g_lvh + (size_t)b * LSZ * DPW;
    const unsigned* Avl = g_lvl + (size_t)b * LSZ * DPW;
    const unsigned* Bvh = g_rvh + (size_t)b * LSZ * DPW;
    const unsigned* Bvl = g_rvl + (size_t)b * LSZ * DPW;

    int tid  = threadIdx.x;
    int lane = tid & 31;
    int wid  = tid >> 5;      // 0..3
    int wm   = wid & 1;       // 2 m-groups of 32
    int wn   = wid >> 1;      // 2 n-groups of 32

    unsigned sbase = (unsigned)__cvta_generic_to_shared(asw);

    // copy coordinates: 2 chunks per operand-half per thread
    const unsigned* pAH[2]; const unsigned* pAL[2];
    const unsigned* pBH[2]; const unsigned* pBL[2];
    unsigned dOf[2]; bool okA[2], okB[2];
#pragma unroll
    for (int q = 0; q < 2; q++) {
        int cid = tid + 128 * q;
        int ar = cid >> 2, ac = cid & 3;
        okA[q] = (m0 + ar) < LSZ;
        okB[q] = (n0 + ar) < LSZ;
        pAH[q] = Avh + (size_t)(okA[q] ? m0 + ar : 0) * DPW + ac * 4;
        pAL[q] = Avl + (size_t)(okA[q] ? m0 + ar : 0) * DPW + ac * 4;
        pBH[q] = Bvh + (size_t)(okB[q] ? n0 + ar : 0) * DPW + ac * 4;
        pBL[q] = Bvl + (size_t)(okB[q] ? n0 + ar : 0) * DPW + ac * 4;
        dOf[q] = ar * CWP + ac * 4;
    }

    float acc[2][4][4];
#pragma unroll
    for (int ms = 0; ms < 2; ms++)
#pragma unroll
        for (int nf = 0; nf < 4; nf++)
#pragma unroll
            for (int q = 0; q < 4; q++) acc[ms][nf][q] = 0.f;

#define ACOPY(kb, s) do {                                                 \
    unsigned sb0 = sbase + (s) * (AST_W * 4);                             \
    _Pragma("unroll")                                                     \
    for (int q = 0; q < 2; q++) {                                         \
        cp16(sb0 + (AST_AH + dOf[q]) * 4, pAH[q] + (kb) * 16, okA[q]);    \
        cp16(sb0 + (AST_AL + dOf[q]) * 4, pAL[q] + (kb) * 16, okA[q]);    \
        cp16(sb0 + (AST_BH + dOf[q]) * 4, pBH[q] + (kb) * 16, okB[q]);    \
        cp16(sb0 + (AST_BL + dOf[q]) * 4, pBL[q] + (kb) * 16, okB[q]);    \
    }                                                                     \
} while (0)

    ACOPY(0, 0);
    cpcommit();

    for (int kb = 0; kb < NKB; kb++) {
        if (kb + 1 < NKB) {
            ACOPY(kb + 1, (kb + 1) & 1);
            cpcommit();
            cpwait<1>();
        } else {
            cpwait<0>();
        }
        __syncthreads();

        unsigned sb0 = sbase + (kb & 1) * (AST_W * 4);
#pragma unroll
        for (int ks = 0; ks < 2; ks++) {
            unsigned ahf[2][4], alf[2][4];
#pragma unroll
            for (int ms = 0; ms < 2; ms++) {
                int r = wm * 32 + ms * 16 + (lane & 7) + ((lane >> 3) & 1) * 8;
                int c = ks * 2 + (lane >> 4);
                ldx4(ahf[ms], sb0 + (AST_AH + r * CWP + c * 4) * 4);
                ldx4(alf[ms], sb0 + (AST_AL + r * CWP + c * 4) * 4);
            }
#pragma unroll
            for (int nfp = 0; nfp < 2; nfp++) {
                int rB = wn * 32 + nfp * 16 + ((lane >> 4) & 1) * 8 + (lane & 7);
                int cB = ks * 2 + ((lane >> 3) & 1);
                unsigned bh[4], bl[4];
                ldx4(bh, sb0 + (AST_BH + rB * CWP + cB * 4) * 4);
                ldx4(bl, sb0 + (AST_BL + rB * CWP + cB * 4) * 4);
#pragma unroll
                for (int ms = 0; ms < 2; ms++) {
                    mma16(acc[ms][2 * nfp],     ahf[ms], bh[0], bh[1]);
                    mma16(acc[ms][2 * nfp],     ahf[ms], bl[0], bl[1]);
                    mma16(acc[ms][2 * nfp],     alf[ms], bh[0], bh[1]);
                    mma16(acc[ms][2 * nfp + 1], ahf[ms], bh[2], bh[3]);
                    mma16(acc[ms][2 * nfp + 1], ahf[ms], bl[2], bl[3]);
                    mma16(acc[ms][2 * nfp + 1], alf[ms], bh[2], bh[3]);
                }
            }
        }
        __syncthreads();
    }
#undef ACOPY

    // stage result in smem [64][68] (aliased over stage buffers)
    float* Ts = (float*)asw;
#pragma unroll
    for (int ms = 0; ms < 2; ms++) {
        int r = wm * 32 + ms * 16 + (lane >> 2);
#pragma unroll
        for (int nf = 0; nf < 4; nf++) {
            int cn = wn * 32 + nf * 8 + 2 * (lane & 3);
            Ts[r * 68 + cn]           = acc[ms][nf][0];
            Ts[r * 68 + cn + 1]       = acc[ms][nf][1];
            Ts[(r + 8) * 68 + cn]     = acc[ms][nf][2];
            Ts[(r + 8) * 68 + cn + 1] = acc[ms][nf][3];
        }
    }
    __syncthreads();

    {   // att[b][l][r]: 128 threads, 2 per row, 8 float4 each
        int row = tid >> 1;
        int coff = (tid & 1) * 32;
        int gm = m0 + row;
        if (gm < LSZ) {
#pragma unroll
            for (int q = 0; q < 8; q++) {
                int cl = coff + q * 4;
                int gn = n0 + cl;
                if (gn < LSZ)
                    *(float4*)(g_att + ((size_t)b * LSZ + gm) * LSZ + gn) =
                        *(const float4*)&Ts[row * 68 + cl];
            }
        }
    }
    {   // attT[b][r][l]
        int rr = tid >> 1;
        int loff = (tid & 1) * 32;
        int gr = n0 + rr;
        if (gr < LSZ) {
#pragma unroll
            for (int q = 0; q < 8; q++) {
                int l0 = loff + q * 4;
                int gl = m0 + l0;
                if (gl < LSZ) {
                    float4 o;
                    o.x = Ts[(l0 + 0) * 68 + rr];
                    o.y = Ts[(l0 + 1) * 68 + rr];
                    o.z = Ts[(l0 + 2) * 68 + rr];
                    o.w = Ts[(l0 + 3) * 68 + rr];
                    *(float4*)(g_attT + ((size_t)b * LSZ + gr) * LSZ + gl) = o;
                }
            }
        }
    }
}

// ---------------- fused softmax / stats / top-3 / counterpart ----------------
__device__ __forceinline__ bool tk_better(float av, int ai, float bv, int bi) {
    return (av > bv) || (av == bv && ai < bi);
}
__device__ __forceinline__ void tk_insert(float nv, int ni,
                                          float& v0, int& i0, float& v1, int& i1, float& v2, int& i2) {
    if (tk_better(nv, ni, v0, i0)) { v2 = v1; i2 = i1; v1 = v0; i1 = i0; v0 = nv; i0 = ni; }
    else if (tk_better(nv, ni, v1, i1)) { v2 = v1; i2 = i1; v1 = nv; i1 = ni; }
    else if (tk_better(nv, ni, v2, i2)) { v2 = nv; i2 = ni; }
}

__global__ void attproc_kernel(const int* __restrict__ ll, const int* __restrict__ rl) {
    int side = blockIdx.y;
    const float* attRows   = side ? g_attT : g_att;
    const unsigned* selfH  = side ? g_rvh : g_lvh;
    const unsigned* selfL  = side ? g_rvl : g_lvl;
    const unsigned* othH   = side ? g_lvh : g_rvh;
    const unsigned* othL   = side ? g_lvl : g_rvl;
    const int* lenSelf     = side ? rl : ll;
    const int* lenOther    = side ? ll : rl;
    unsigned* outX         = side ? g_rcx : g_lcx;

    int wid  = blockIdx.x * (blockDim.x >> 5) + (threadIdx.x >> 5);
    int lane = threadIdx.x & 31;
    int b = wid / LSZ, i = wid % LSZ;
    if (b >= BSZ) return;
    if (i >= lenSelf[b]) return;
    int n = lenOther[b];
    const float* row = attRows + ((size_t)b * LSZ + i) * LSZ;
    const unsigned FULL = 0xffffffffu;

    float rv[5];
#pragma unroll
    for (int k = 0; k < 5; k++) {
        int j = lane + 32 * k;
        rv[k] = (j < n) ? row[j] : -3.0e38f;
    }

    float v0 = -3.0e38f, v1 = -3.0e38f, v2 = -3.0e38f;
    int i0 = 0x7fffffff, i1 = 0x7fffffff, i2 = 0x7fffffff;
#pragma unroll
    for (int k = 0; k < 5; k++) {
        int j = lane + 32 * k;
        if (j < n) tk_insert(rv[k], j, v0, i0, v1, i1, v2, i2);
    }
#pragma unroll
    for (int off = 16; off >= 1; off >>= 1) {
        float ov0 = __shfl_xor_sync(FULL, v0, off);
        int   oi0 = __shfl_xor_sync(FULL, i0, off);
        float ov1 = __shfl_xor_sync(FULL, v1, off);
        int   oi1 = __shfl_xor_sync(FULL, i1, off);
        float ov2 = __shfl_xor_sync(FULL, v2, off);
        int   oi2 = __shfl_xor_sync(FULL, i2, off);
        tk_insert(ov0, oi0, v0, i0, v1, i1, v2, i2);
        tk_insert(ov1, oi1, v0, i0, v1, i1, v2, i2);
        tk_insert(ov2, oi2, v0, i0, v1, i1, v2, i2);
    }
    float m = v0;

    float S = 0.f, S2 = 0.f;
#pragma unroll
    for (int k = 0; k < 5; k++) {
        int j = lane + 32 * k;
        if (j < n) {
            float e = expf(rv[k] - m);
            S += e; S2 += e * e;
        }
    }
#pragma unroll
    for (int off = 16; off >= 1; off >>= 1) {
        S  += __shfl_xor_sync(FULL, S,  off);
        S2 += __shfl_xor_sync(FULL, S2, off);
    }

    float rlenf = (float)n;
    float mean  = 1.0f / rlenf;
    float s2    = S2 / (S * S);
    float w     = (s2 / rlenf - mean * mean) / fmaxf(mean, 0.001f);

    float a0 = 1.0f, a1 = expf(v1 - v0), a2 = expf(v2 - v0);
    float asum = a0 + a1 + a2;
    a0 /= asum; a1 /= asum; a2 /= asum;

    size_t r0 = ((size_t)b * LSZ + i0) * DPW;
    size_t r1 = ((size_t)b * LSZ + i1) * DPW;
    size_t r2 = ((size_t)b * LSZ + i2) * DPW;
    size_t rs = ((size_t)b * LSZ + i) * DPW;

#pragma unroll
    for (int k = 0; k < 6; k++) {
        int p = lane + 32 * k;
        if (p < DPW) {
            float x0 = 0.f, x1 = 0.f;
            if (p < 175) {
                float2 e0 = rec2(othH[r0 + p], othL[r0 + p]);
                float2 e1 = rec2(othH[r1 + p], othL[r1 + p]);
                float2 e2 = rec2(othH[r2 + p], othL[r2 + p]);
                float2 s  = rec2(selfH[rs + p], selfL[rs + p]);
                float c0 = a0 * e0.x + a1 * e1.x + a2 * e2.x;
                float c1 = a0 * e0.y + a1 * e1.y + a2 * e2.y;
                x0 = w * fabsf(s.x - c0);
                x1 = w * fabsf(s.y - c1);
            }
            __half2 hx = __floats2half2_rn(x0, x1);
            outX[rs + p] = *(unsigned*)&hx;
        }
    }
}

// =====================================================================
// conv GEMM fused with relu-max pooling (unchanged from round 9)
// =====================================================================
#define STG_W  (64 * CWP + 128 * CWP + 128 * CWP)
#define OFF_A  0
#define OFF_BH (64 * CWP)
#define OFF_BL (64 * CWP + 128 * CWP)

__global__ __launch_bounds__(256) void conv_gemm_kernel(const int* __restrict__ llen,
                                                        const int* __restrict__ rlen,
                                                        const float* __restrict__ cb1,
                                                        const float* __restrict__ cb2,
                                                        const float* __restrict__ cb3) {
    extern __shared__ unsigned smw[];
    int zb = blockIdx.z;
    int side = zb >> 9, b = zb & 511;
    int m0 = blockIdx.x * 62;          // overlapped m-tiles: 0, 62, 124
    int tileN = blockIdx.y;            // 0..4
    int len = side ? rlen[b] : llen[b];
    if (m0 >= len) return;

    const unsigned* Ax = (side ? g_rcx : g_lcx) + (size_t)b * LSZ * DPW;
    int n0 = tileN * 128;

    int tid  = threadIdx.x;
    int lane = tid & 31;
    int wid  = tid >> 5;
    int wm   = wid & 1;
    int wn   = wid >> 1;

    unsigned sbase = (unsigned)__cvta_generic_to_shared(smw);

    int ar = tid >> 2, ac = tid & 3;
    int agm = m0 + ar;
    bool aok = agm < LSZ;
    const unsigned* asrc = Ax + (size_t)(aok ? agm : 0) * DPW + ac * 4;
    unsigned adst = (OFF_A + ar * CWP + ac * 4);

    float acc[2][4][4];
#pragma unroll
    for (int ms = 0; ms < 2; ms++)
#pragma unroll
        for (int nf = 0; nf < 4; nf++)
#pragma unroll
            for (int q = 0; q < 4; q++) acc[ms][nf][q] = 0.f;

#define COPY_STAGE(kb, s) do {                                                    \
    unsigned sb0 = sbase + (s) * (STG_W * 4);                                     \
    cp16(sb0 + adst * 4, asrc + (kb) * 16, aok);                                  \
    _Pragma("unroll")                                                             \
    for (int q = 0; q < 2; q++) {                                                 \
        int cid = tid + 256 * q;                                                  \
        int br = cid >> 2, bc = cid & 3;                                          \
        cp16(sb0 + (OFF_BH + br * CWP + bc * 4) * 4,                              \
             g_wallh + (size_t)(n0 + br) * DPW + (kb) * 16 + bc * 4, true);       \
        cp16(sb0 + (OFF_BL + br * CWP + bc * 4) * 4,                              \
             g_walll + (size_t)(n0 + br) * DPW + (kb) * 16 + bc * 4, true);       \
    }                                                                             \
} while (0)

    COPY_STAGE(0, 0);
    cpcommit();

    for (int kb = 0; kb < NKB; kb++) {
        if (kb + 1 < NKB) {
            COPY_STAGE(kb + 1, (kb + 1) & 1);
            cpcommit();
            cpwait<1>();
        } else {
            cpwait<0>();
        }
        __syncthreads();

        unsigned sb0 = sbase + (kb & 1) * (STG_W * 4);
#pragma unroll
        for (int ks = 0; ks < 2; ks++) {
            unsigned af[2][4];
#pragma unroll
            for (int ms = 0; ms < 2; ms++) {
                int r = wm * 32 + ms * 16 + (lane & 7) + ((lane >> 3) & 1) * 8;
                int c = ks * 2 + (lane >> 4);
                ldx4(af[ms], sb0 + (OFF_A + r * CWP + c * 4) * 4);
            }
#pragma unroll
            for (int nfp = 0; nfp < 2; nfp++) {
                int rB = wn * 32 + nfp * 16 + ((lane >> 4) & 1) * 8 + (lane & 7);
                int cB = ks * 2 + ((lane >> 3) & 1);
                unsigned bh[4], bl[4];
                ldx4(bh, sb0 + (OFF_BH + rB * CWP + cB * 4) * 4);
                ldx4(bl, sb0 + (OFF_BL + rB * CWP + cB * 4) * 4);
#pragma unroll
                for (int ms = 0; ms < 2; ms++) {
                    mma16h(acc[ms][2 * nfp],     af[ms], bh[0], bh[1]);
                    mma16h(acc[ms][2 * nfp],     af[ms], bl[0], bl[1]);
                    mma16h(acc[ms][2 * nfp + 1], af[ms], bh[2], bh[3]);
                    mma16h(acc[ms][2 * nfp + 1], af[ms], bl[2], bl[3]);
                }
            }
        }
        __syncthreads();
    }
#undef COPY_STAGE

    float* Zs = (float*)smw;          // [64][ZPITCH]
#pragma unroll
    for (int ms = 0; ms < 2; ms++) {
        int r = wm * 32 + ms * 16 + (lane >> 2);
#pragma unroll
        for (int nf = 0; nf < 4; nf++) {
            int jc = wn * 32 + nf * 8 + 2 * (lane & 3);
            Zs[r * ZPITCH + jc]           = acc[ms][nf][0];
            Zs[r * ZPITCH + jc + 1]       = acc[ms][nf][1];
            Zs[(r + 8) * ZPITCH + jc]     = acc[ms][nf][2];
            Zs[(r + 8) * ZPITCH + jc + 1] = acc[ms][nf][3];
        }
    }
    __syncthreads();

    if (tid < 60) {
        int o_l = tid / 3, cv = tid % 3;
        int o_g = tileN * 20 + o_l;
        if (o_g < 100) {
            int cb = o_l * 6;
            float bias = (cv == 0) ? cb1[o_g] : (cv == 1 ? cb2[o_g] : cb3[o_g]);
            float mx = 0.f;
            int k = cv + 1;
            int tmax = min(64 - k, len - k - m0);
            if (cv == 0) {
                for (int t = 0; t <= tmax; t++)
                    mx = fmaxf(mx, Zs[t * ZPITCH + cb] + bias);
            } else if (cv == 1) {
                for (int t = 0; t <= tmax; t++)
                    mx = fmaxf(mx, Zs[t * ZPITCH + cb + 1] + Zs[(t + 1) * ZPITCH + cb + 2] + bias);
            } else {
                for (int t = 0; t <= tmax; t++)
                    mx = fmaxf(mx, Zs[t * ZPITCH + cb + 3] + Zs[(t + 1) * ZPITCH + cb + 4]
                                 + Zs[(t + 2) * ZPITCH + cb + 5] + bias);
            }
            int fidx = b * NCH + side * 300 + cv * 100 + o_g;
            atomicMax((int*)&g_feats[fidx], __float_as_int(mx));
        }
    }
}

// ---------------- dense head ----------------
__global__ void dense_kernel(const float* __restrict__ dw1, const float* __restrict__ db1,
                             const float* __restrict__ dw2, const float* __restrict__ db2,
                             float* __restrict__ out) {
    int b = blockIdx.x;
    __shared__ float f[NCH];
    __shared__ float h[64];
    int tid = threadIdx.x;
    for (int j = tid; j < NCH; j += blockDim.x) f[j] = g_feats[(size_t)b * NCH + j];
    __syncthreads();
    if (tid < 60) {
        float s = db1[tid];
        for (int j = 0; j < NCH; j++) s += f[j] * dw1[j * 60 + tid];
        h[tid] = fmaxf(s, 0.f);
    }
    __syncthreads();
    if (tid < 2) {
        float s = db2[tid];
        for (int j = 0; j < 60; j++) s += h[j] * dw2[j * 2 + tid];
        out[b * 2 + tid] = s;
    }
}

// ---------------- launch ----------------
extern "C" void kernel_launch(void* const* d_in, const int* in_sizes, int n_in,
                              void* d_out, int out_size) {
    const int*   lt   = (const int*)d_in[0];
    const int*   la   = (const int*)d_in[1];
    const int*   ll   = (const int*)d_in[2];
    const int*   rt   = (const int*)d_in[3];
    const int*   ra   = (const int*)d_in[4];
    const int*   rl   = (const int*)d_in[5];
    const float* wemb = (const float*)d_in[6];
    const float* aemb = (const float*)d_in[7];
    const float* cw1  = (const float*)d_in[8];
    const float* cb1  = (const float*)d_in[9];
    const float* cw2  = (const float*)d_in[10];
    const float* cb2  = (const float*)d_in[11];
    const float* cw3  = (const float*)d_in[12];
    const float* cb3  = (const float*)d_in[13];
    const float* dw1  = (const float*)d_in[14];
    const float* db1  = (const float*)d_in[15];
    const float* dw2  = (const float*)d_in[16];
    const float* db2  = (const float*)d_in[17];
    float* out = (float*)d_out;

    const int convSmem = STG_W * 4 * 2;   // 51200 bytes
    const int attSmem  = AST_W * 4 * 2;   // 40960 bytes
    cudaFuncSetAttribute(conv_gemm_kernel,
                         cudaFuncAttributeMaxDynamicSharedMemorySize, convSmem);
    cudaFuncSetAttribute(att_gemm_kernel,
                         cudaFuncAttributeMaxDynamicSharedMemorySize, attSmem);

    init_kernel<<<(BSZ * NCH + 255) / 256, 256>>>(cw1, cw2, cw3);
    gather_kernel<<<dim3(LSZ, BSZ, 2), 96>>>(lt, la, rt, ra, wemb, aemb, ll, rl);
    att_gemm_kernel<<<dim3(3, 3, BSZ), 128, attSmem>>>(ll, rl);
    attproc_kernel<<<dim3((BSZ * LSZ) / 4, 2), 128>>>(ll, rl);
    conv_gemm_kernel<<<dim3(3, 5, 2 * BSZ), 256, convSmem>>>(ll, rl, cb1, cb2, cb3);
    dense_kernel<<<BSZ, 128>>>(dw1, db1, dw2, db2, out);
}

// round 11
// speedup vs baseline: 1.0653x; 1.0653x over previous
#include <cuda_runtime.h>
#include <cuda_bf16.h>
#include <cuda_fp16.h>
#include <math.h>
#include <stdint.h>

// ---------------- problem constants ----------------
#define BSZ   512
#define LSZ   160
#define DDIM  350
#define DP    352     // padded D
#define DPW   176     // DP/2 packed words
#define NCH   600
#define NPAD  640
#define CWP   20      // smem word pitch (16 + 4 pad)
#define ZPITCH 132    // conv Z smem pitch

// ---------------- device scratch ----------------
__device__ unsigned g_lvh [(size_t)BSZ * LSZ * DPW];   // l_vec split hi (bf16x2)
__device__ unsigned g_lvl [(size_t)BSZ * LSZ * DPW];   // l_vec split lo
__device__ unsigned g_rvh [(size_t)BSZ * LSZ * DPW];
__device__ unsigned g_rvl [(size_t)BSZ * LSZ * DPW];
__device__ float    g_att [(size_t)BSZ * LSZ * LSZ];
__device__ float    g_attT[(size_t)BSZ * LSZ * LSZ];
__device__ unsigned g_lcx [(size_t)BSZ * LSZ * DPW];   // l_c as half2
__device__ unsigned g_rcx [(size_t)BSZ * LSZ * DPW];   // r_c as half2
__device__ unsigned g_wallh[(size_t)NPAD * DPW];       // wall fp16 hi (half2)
__device__ unsigned g_walll[(size_t)NPAD * DPW];       // wall fp16 lo (half2)
__device__ float    g_feats[(size_t)BSZ * NCH];

// ---------------- split helpers ----------------
__device__ __forceinline__ void split2(float a, float b, unsigned& hi, unsigned& lo) {
    __nv_bfloat162 h = __floats2bfloat162_rn(a, b);
    float ra = a - __bfloat162float(h.x);
    float rb = b - __bfloat162float(h.y);
    __nv_bfloat162 l = __floats2bfloat162_rn(ra, rb);
    hi = *(unsigned*)&h;
    lo = *(unsigned*)&l;
}
__device__ __forceinline__ void split2h(float a, float b, unsigned& hi, unsigned& lo) {
    __half2 h = __floats2half2_rn(a, b);
    float ra = a - __half2float(__low2half(h));
    float rb = b - __half2float(__high2half(h));
    __half2 l = __floats2half2_rn(ra, rb);
    hi = *(unsigned*)&h;
    lo = *(unsigned*)&l;
}
__device__ __forceinline__ float2 rec2(unsigned h, unsigned l) {
    __nv_bfloat162 hb = *(__nv_bfloat162*)&h;
    __nv_bfloat162 lb = *(__nv_bfloat162*)&l;
    float2 r;
    r.x = __bfloat162float(hb.x) + __bfloat162float(lb.x);
    r.y = __bfloat162float(hb.y) + __bfloat162float(lb.y);
    return r;
}
__device__ __forceinline__ void mma16(float* c, const unsigned* a, unsigned b0, unsigned b1) {
    asm volatile(
        "mma.sync.aligned.m16n8k16.row.col.f32.bf16.bf16.f32 "
        "{%0,%1,%2,%3}, {%4,%5,%6,%7}, {%8,%9}, {%0,%1,%2,%3};"
        : "+f"(c[0]), "+f"(c[1]), "+f"(c[2]), "+f"(c[3])
        : "r"(a[0]), "r"(a[1]), "r"(a[2]), "r"(a[3]), "r"(b0), "r"(b1));
}
__device__ __forceinline__ void mma16h(float* c, const unsigned* a, unsigned b0, unsigned b1) {
    asm volatile(
        "mma.sync.aligned.m16n8k16.row.col.f32.f16.f16.f32 "
        "{%0,%1,%2,%3}, {%4,%5,%6,%7}, {%8,%9}, {%0,%1,%2,%3};"
        : "+f"(c[0]), "+f"(c[1]), "+f"(c[2]), "+f"(c[3])
        : "r"(a[0]), "r"(a[1]), "r"(a[2]), "r"(a[3]), "r"(b0), "r"(b1));
}
__device__ __forceinline__ void ldx4(unsigned* r, unsigned addr) {
    asm volatile("ldmatrix.sync.aligned.m8n8.x4.shared.b16 {%0,%1,%2,%3}, [%4];"
                 : "=r"(r[0]), "=r"(r[1]), "=r"(r[2]), "=r"(r[3]) : "r"(addr));
}
__device__ __forceinline__ void cp16(unsigned dst, const void* src, bool pred) {
    int sz = pred ? 16 : 0;
    asm volatile("cp.async.ca.shared.global [%0], [%1], 16, %2;"
                 :: "r"(dst), "l"(src), "r"(sz));
}
__device__ __forceinline__ void cpcommit() { asm volatile("cp.async.commit_group;"); }
template<int N> __device__ __forceinline__ void cpwait() {
    asm volatile("cp.async.wait_group %0;" :: "n"(N));
}

// ---------------- merged init: zero feats + build permuted fp16-split wall ------
__global__ void init_kernel(const float* __restrict__ w1,
                            const float* __restrict__ w2,
                            const float* __restrict__ w3) {
    int idx = blockIdx.x * blockDim.x + threadIdx.x;
    if (idx < BSZ * NCH) g_feats[idx] = 0.f;
    if (idx < NPAD * DPW) {
        int nn = idx / DPW, p = idx % DPW;
        int tile = nn >> 7, j = nn & 127;
        int o = tile * 20 + j / 6;
        int g = j % 6;
        bool valid = (j < 120) && (o < 100);
        float v[2];
#pragma unroll
        for (int c = 0; c < 2; c++) {
            int k = 2 * p + c;
            float x = 0.f;
            if (valid && k < DDIM) {
                if      (g == 0) x = w1[o * DDIM + k];
                else if (g <= 2) x = w2[o * (DDIM * 2) + k * 2 + (g - 1)];
                else             x = w3[o * (DDIM * 3) + k * 3 + (g - 3)];
            }
            v[c] = x;
        }
        unsigned hi, lo;
        split2h(v[0], v[1], hi, lo);
        g_wallh[idx] = hi;
        g_walll[idx] = lo;
    }
}

// ---------------- embedding gather (len-trimmed) -> pre-split bf16 hi/lo --------
__global__ void gather_kernel(const int* __restrict__ lt, const int* __restrict__ la,
                              const int* __restrict__ rt, const int* __restrict__ ra,
                              const float* __restrict__ wemb, const float* __restrict__ aemb,
                              const int* __restrict__ ll, const int* __restrict__ rl) {
    int l = blockIdx.x, b = blockIdx.y, side = blockIdx.z;
    int len = side ? rl[b] : ll[b];
    if (l >= len) return;                    // rows >= len are never read downstream
    const int* tok = side ? rt : lt;
    const int* atr = side ? ra : la;
    size_t rowo = ((size_t)(b * LSZ + l)) * DPW;
    unsigned* dstH = (side ? g_rvh : g_lvh) + rowo;
    unsigned* dstL = (side ? g_rvl : g_lvl) + rowo;
    int t = tok[l * BSZ + b];
    int a = atr[l * BSZ + b];
    const float* wr = wemb + (size_t)t * 300;
    const float* ar = aemb + (size_t)a * 50;
    int q = threadIdx.x;
    if (q < 88) {
        int d0 = q * 4;
        float v[4];
#pragma unroll
        for (int c = 0; c < 4; c++) {
            int d = d0 + c;
            float x = 0.f;
            if (d < 50) x = __ldg(ar + d);
            else if (d < DDIM) x = __ldg(wr + d - 50);
            v[c] = x;
        }
        unsigned hi, lo;
        split2(v[0], v[1], hi, lo);
        dstH[q * 2] = hi; dstL[q * 2] = lo;
        split2(v[2], v[3], hi, lo);
        dstH[q * 2 + 1] = hi; dstL[q * 2 + 1] = lo;
    }
}

// =====================================================================
// att GEMM (round-9 proven): 64x64 tile, 8 warps (2m x 4n, 32x16 warp
// tiles), cp.async 2-stage + ldmatrix, bf16 3-term split.
// =====================================================================
#define AST_AH 0
#define AST_AL (64 * CWP)
#define AST_BH (2 * 64 * CWP)
#define AST_BL (3 * 64 * CWP)
#define AST_W  (4 * 64 * CWP)
#define NKB    11

__global__ __launch_bounds__(256) void att_gemm_kernel(const int* __restrict__ llen,
                                                       const int* __restrict__ rlen) {
    extern __shared__ unsigned asw[];
    int b  = blockIdx.z;
    int m0 = blockIdx.x * 64;
    int n0 = blockIdx.y * 64;
    if (m0 >= llen[b] || n0 >= rlen[b]) return;

    const unsigned* Avh = g_lvh + (size_t)b * LSZ * DPW;
    const unsigned* Avl = g_lvl + (size_t)b * LSZ * DPW;
    const unsigned* Bvh = g_rvh + (size_t)b * LSZ * DPW;
    const unsigned* Bvl = g_rvl + (size_t)b * LSZ * DPW;

    int tid  = threadIdx.x;
    int lane = tid & 31;
    int wid  = tid >> 5;
    int wm   = wid & 1;
    int wn   = wid >> 1;

    unsigned sbase = (unsigned)__cvta_generic_to_shared(asw);

    int ar = tid >> 2, ac = tid & 3;
    bool aok = (m0 + ar) < LSZ;
    bool bok = (n0 + ar) < LSZ;
    const unsigned* asH = Avh + (size_t)(aok ? m0 + ar : 0) * DPW + ac * 4;
    const unsigned* asL = Avl + (size_t)(aok ? m0 + ar : 0) * DPW + ac * 4;
    const unsigned* bsH = Bvh + (size_t)(bok ? n0 + ar : 0) * DPW + ac * 4;
    const unsigned* bsL = Bvl + (size_t)(bok ? n0 + ar : 0) * DPW + ac * 4;
    unsigned dA = (ar * CWP + ac * 4);

    float acc[2][2][4];
#pragma unroll
    for (int ms = 0; ms < 2; ms++)
#pragma unroll
        for (int nf = 0; nf < 2; nf++)
#pragma unroll
            for (int q = 0; q < 4; q++) acc[ms][nf][q] = 0.f;

#define ACOPY(kb, s) do {                                                \
    unsigned sb0 = sbase + (s) * (AST_W * 4);                            \
    cp16(sb0 + (AST_AH + dA) * 4, asH + (kb) * 16, aok);                 \
    cp16(sb0 + (AST_AL + dA) * 4, asL + (kb) * 16, aok);                 \
    cp16(sb0 + (AST_BH + dA) * 4, bsH + (kb) * 16, bok);                 \
    cp16(sb0 + (AST_BL + dA) * 4, bsL + (kb) * 16, bok);                 \
} while (0)

    ACOPY(0, 0);
    cpcommit();

    for (int kb = 0; kb < NKB; kb++) {
        if (kb + 1 < NKB) {
            ACOPY(kb + 1, (kb + 1) & 1);
            cpcommit();
            cpwait<1>();
        } else {
            cpwait<0>();
        }
        __syncthreads();

        unsigned sb0 = sbase + (kb & 1) * (AST_W * 4);
#pragma unroll
        for (int ks = 0; ks < 2; ks++) {
            unsigned ahf[2][4], alf[2][4];
#pragma unroll
            for (int ms = 0; ms < 2; ms++) {
                int r = wm * 32 + ms * 16 + (lane & 7) + ((lane >> 3) & 1) * 8;
                int c = ks * 2 + (lane >> 4);
                ldx4(ahf[ms], sb0 + (AST_AH + r * CWP + c * 4) * 4);
                ldx4(alf[ms], sb0 + (AST_AL + r * CWP + c * 4) * 4);
            }
            int rB = wn * 16 + ((lane >> 4) & 1) * 8 + (lane & 7);
            int cB = ks * 2 + ((lane >> 3) & 1);
            unsigned bh[4], bl[4];
            ldx4(bh, sb0 + (AST_BH + rB * CWP + cB * 4) * 4);
            ldx4(bl, sb0 + (AST_BL + rB * CWP + cB * 4) * 4);
#pragma unroll
            for (int ms = 0; ms < 2; ms++) {
                mma16(acc[ms][0], ahf[ms], bh[0], bh[1]);
                mma16(acc[ms][0], ahf[ms], bl[0], bl[1]);
                mma16(acc[ms][0], alf[ms], bh[0], bh[1]);
                mma16(acc[ms][1], ahf[ms], bh[2], bh[3]);
                mma16(acc[ms][1], ahf[ms], bl[2], bl[3]);
                mma16(acc[ms][1], alf[ms], bh[2], bh[3]);
            }
        }
        __syncthreads();
    }
#undef ACOPY

    float* Ts = (float*)asw;
#pragma unroll
    for (int ms = 0; ms < 2; ms++) {
        int r = wm * 32 + ms * 16 + (lane >> 2);
#pragma unroll
        for (int nf = 0; nf < 2; nf++) {
            int cn = wn * 16 + nf * 8 + 2 * (lane & 3);
            Ts[r * 68 + cn]           = acc[ms][nf][0];
            Ts[r * 68 + cn + 1]       = acc[ms][nf][1];
            Ts[(r + 8) * 68 + cn]     = acc[ms][nf][2];
            Ts[(r + 8) * 68 + cn + 1] = acc[ms][nf][3];
        }
    }
    __syncthreads();

    {
        int row = tid >> 2;
        int gm = m0 + row;
        if (gm < LSZ) {
#pragma unroll
            for (int q = 0; q < 4; q++) {
                int cl = (tid & 3) * 16 + q * 4;
                int gn = n0 + cl;
                if (gn < LSZ)
                    *(float4*)(g_att + ((size_t)b * LSZ + gm) * LSZ + gn) =
                        *(const float4*)&Ts[row * 68 + cl];
            }
        }
    }
    {
        int rr = tid >> 2;
        int gr = n0 + rr;
        if (gr < LSZ) {
#pragma unroll
            for (int q = 0; q < 4; q++) {
                int l0 = (tid & 3) * 16 + q * 4;
                int gl = m0 + l0;
                if (gl < LSZ) {
                    float4 o;
                    o.x = Ts[(l0 + 0) * 68 + rr];
                    o.y = Ts[(l0 + 1) * 68 + rr];
                    o.z = Ts[(l0 + 2) * 68 + rr];
                    o.w = Ts[(l0 + 3) * 68 + rr];
                    *(float4*)(g_attT + ((size_t)b * LSZ + gr) * LSZ + gl) = o;
                }
            }
        }
    }
}

// ---------------- fused softmax / stats / top-3 / counterpart ----------------
__device__ __forceinline__ bool tk_better(float av, int ai, float bv, int bi) {
    return (av > bv) || (av == bv && ai < bi);
}
__device__ __forceinline__ void tk_insert(float nv, int ni,
                                          float& v0, int& i0, float& v1, int& i1, float& v2, int& i2) {
    if (tk_better(nv, ni, v0, i0)) { v2 = v1; i2 = i1; v1 = v0; i1 = i0; v0 = nv; i0 = ni; }
    else if (tk_better(nv, ni, v1, i1)) { v2 = v1; i2 = i1; v1 = nv; i1 = ni; }
    else if (tk_better(nv, ni, v2, i2)) { v2 = nv; i2 = ni; }
}

__global__ void attproc_kernel(const int* __restrict__ ll, const int* __restrict__ rl) {
    int side = blockIdx.y;
    const float* attRows   = side ? g_attT : g_att;
    const unsigned* selfH  = side ? g_rvh : g_lvh;
    const unsigned* selfL  = side ? g_rvl : g_lvl;
    const unsigned* othH   = side ? g_lvh : g_rvh;
    const unsigned* othL   = side ? g_lvl : g_rvl;
    const int* lenSelf     = side ? rl : ll;
    const int* lenOther    = side ? ll : rl;
    unsigned* outX         = side ? g_rcx : g_lcx;

    int wid  = blockIdx.x * (blockDim.x >> 5) + (threadIdx.x >> 5);
    int lane = threadIdx.x & 31;
    int b = wid / LSZ, i = wid % LSZ;
    if (b >= BSZ) return;
    if (i >= lenSelf[b]) return;
    int n = lenOther[b];
    const float* row = attRows + ((size_t)b * LSZ + i) * LSZ;
    const unsigned FULL = 0xffffffffu;

    float rv[5];
#pragma unroll
    for (int k = 0; k < 5; k++) {
        int j = lane + 32 * k;
        rv[k] = (j < n) ? row[j] : -3.0e38f;
    }

    float v0 = -3.0e38f, v1 = -3.0e38f, v2 = -3.0e38f;
    int i0 = 0x7fffffff, i1 = 0x7fffffff, i2 = 0x7fffffff;
#pragma unroll
    for (int k = 0; k < 5; k++) {
        int j = lane + 32 * k;
        if (j < n) tk_insert(rv[k], j, v0, i0, v1, i1, v2, i2);
    }
#pragma unroll
    for (int off = 16; off >= 1; off >>= 1) {
        float ov0 = __shfl_xor_sync(FULL, v0, off);
        int   oi0 = __shfl_xor_sync(FULL, i0, off);
        float ov1 = __shfl_xor_sync(FULL, v1, off);
        int   oi1 = __shfl_xor_sync(FULL, i1, off);
        float ov2 = __shfl_xor_sync(FULL, v2, off);
        int   oi2 = __shfl_xor_sync(FULL, i2, off);
        tk_insert(ov0, oi0, v0, i0, v1, i1, v2, i2);
        tk_insert(ov1, oi1, v0, i0, v1, i1, v2, i2);
        tk_insert(ov2, oi2, v0, i0, v1, i1, v2, i2);
    }
    float m = v0;

    float S = 0.f, S2 = 0.f;
#pragma unroll
    for (int k = 0; k < 5; k++) {
        int j = lane + 32 * k;
        if (j < n) {
            float e = expf(rv[k] - m);
            S += e; S2 += e * e;
        }
    }
#pragma unroll
    for (int off = 16; off >= 1; off >>= 1) {
        S  += __shfl_xor_sync(FULL, S,  off);
        S2 += __shfl_xor_sync(FULL, S2, off);
    }

    float rlenf = (float)n;
    float mean  = 1.0f / rlenf;
    float s2    = S2 / (S * S);
    float w     = (s2 / rlenf - mean * mean) / fmaxf(mean, 0.001f);

    float a0 = 1.0f, a1 = expf(v1 - v0), a2 = expf(v2 - v0);
    float asum = a0 + a1 + a2;
    a0 /= asum; a1 /= asum; a2 /= asum;

    size_t r0 = ((size_t)b * LSZ + i0) * DPW;
    size_t r1 = ((size_t)b * LSZ + i1) * DPW;
    size_t r2 = ((size_t)b * LSZ + i2) * DPW;
    size_t rs = ((size_t)b * LSZ + i) * DPW;

#pragma unroll
    for (int k = 0; k < 6; k++) {
        int p = lane + 32 * k;
        if (p < DPW) {
            float x0 = 0.f, x1 = 0.f;
            if (p < 175) {
                float2 e0 = rec2(othH[r0 + p], othL[r0 + p]);
                float2 e1 = rec2(othH[r1 + p], othL[r1 + p]);
                float2 e2 = rec2(othH[r2 + p], othL[r2 + p]);
                float2 s  = rec2(selfH[rs + p], selfL[rs + p]);
                float c0 = a0 * e0.x + a1 * e1.x + a2 * e2.x;
                float c1 = a0 * e0.y + a1 * e1.y + a2 * e2.y;
                x0 = w * fabsf(s.x - c0);
                x1 = w * fabsf(s.y - c1);
            }
            __half2 hx = __floats2half2_rn(x0, x1);
            outX[rs + p] = *(unsigned*)&hx;
        }
    }
}

// =====================================================================
// conv GEMM fused with relu-max pooling (round-9 proven, unchanged)
// =====================================================================
#define STG_W  (64 * CWP + 128 * CWP + 128 * CWP)
#define OFF_A  0
#define OFF_BH (64 * CWP)
#define OFF_BL (64 * CWP + 128 * CWP)

__global__ __launch_bounds__(256) void conv_gemm_kernel(const int* __restrict__ llen,
                                                        const int* __restrict__ rlen,
                                                        const float* __restrict__ cb1,
                                                        const float* __restrict__ cb2,
                                                        const float* __restrict__ cb3) {
    extern __shared__ unsigned smw[];
    int zb = blockIdx.z;
    int side = zb >> 9, b = zb & 511;
    int m0 = blockIdx.x * 62;          // overlapped m-tiles: 0, 62, 124
    int tileN = blockIdx.y;            // 0..4
    int len = side ? rlen[b] : llen[b];
    if (m0 >= len) return;

    const unsigned* Ax = (side ? g_rcx : g_lcx) + (size_t)b * LSZ * DPW;
    int n0 = tileN * 128;

    int tid  = threadIdx.x;
    int lane = tid & 31;
    int wid  = tid >> 5;
    int wm   = wid & 1;
    int wn   = wid >> 1;

    unsigned sbase = (unsigned)__cvta_generic_to_shared(smw);

    int ar = tid >> 2, ac = tid & 3;
    int agm = m0 + ar;
    bool aok = agm < LSZ;
    const unsigned* asrc = Ax + (size_t)(aok ? agm : 0) * DPW + ac * 4;
    unsigned adst = (OFF_A + ar * CWP + ac * 4);

    float acc[2][4][4];
#pragma unroll
    for (int ms = 0; ms < 2; ms++)
#pragma unroll
        for (int nf = 0; nf < 4; nf++)
#pragma unroll
            for (int q = 0; q < 4; q++) acc[ms][nf][q] = 0.f;

#define COPY_STAGE(kb, s) do {                                                    \
    unsigned sb0 = sbase + (s) * (STG_W * 4);                                     \
    cp16(sb0 + adst * 4, asrc + (kb) * 16, aok);                                  \
    _Pragma("unroll")                                                             \
    for (int q = 0; q < 2; q++) {                                                 \
        int cid = tid + 256 * q;                                                  \
        int br = cid >> 2, bc = cid & 3;                                          \
        cp16(sb0 + (OFF_BH + br * CWP + bc * 4) * 4,                              \
             g_wallh + (size_t)(n0 + br) * DPW + (kb) * 16 + bc * 4, true);       \
        cp16(sb0 + (OFF_BL + br * CWP + bc * 4) * 4,                              \
             g_walll + (size_t)(n0 + br) * DPW + (kb) * 16 + bc * 4, true);       \
    }                                                                             \
} while (0)

    COPY_STAGE(0, 0);
    cpcommit();

    for (int kb = 0; kb < NKB; kb++) {
        if (kb + 1 < NKB) {
            COPY_STAGE(kb + 1, (kb + 1) & 1);
            cpcommit();
            cpwait<1>();
        } else {
            cpwait<0>();
        }
        __syncthreads();

        unsigned sb0 = sbase + (kb & 1) * (STG_W * 4);
#pragma unroll
        for (int ks = 0; ks < 2; ks++) {
            unsigned af[2][4];
#pragma unroll
            for (int ms = 0; ms < 2; ms++) {
                int r = wm * 32 + ms * 16 + (lane & 7) + ((lane >> 3) & 1) * 8;
                int c = ks * 2 + (lane >> 4);
                ldx4(af[ms], sb0 + (OFF_A + r * CWP + c * 4) * 4);
            }
#pragma unroll
            for (int nfp = 0; nfp < 2; nfp++) {
                int rB = wn * 32 + nfp * 16 + ((lane >> 4) & 1) * 8 + (lane & 7);
                int cB = ks * 2 + ((lane >> 3) & 1);
                unsigned bh[4], bl[4];
                ldx4(bh, sb0 + (OFF_BH + rB * CWP + cB * 4) * 4);
                ldx4(bl, sb0 + (OFF_BL + rB * CWP + cB * 4) * 4);
#pragma unroll
                for (int ms = 0; ms < 2; ms++) {
                    mma16h(acc[ms][2 * nfp],     af[ms], bh[0], bh[1]);
                    mma16h(acc[ms][2 * nfp],     af[ms], bl[0], bl[1]);
                    mma16h(acc[ms][2 * nfp + 1], af[ms], bh[2], bh[3]);
                    mma16h(acc[ms][2 * nfp + 1], af[ms], bl[2], bl[3]);
                }
            }
        }
        __syncthreads();
    }
#undef COPY_STAGE

    float* Zs = (float*)smw;          // [64][ZPITCH]
#pragma unroll
    for (int ms = 0; ms < 2; ms++) {
        int r = wm * 32 + ms * 16 + (lane >> 2);
#pragma unroll
        for (int nf = 0; nf < 4; nf++) {
            int jc = wn * 32 + nf * 8 + 2 * (lane & 3);
            Zs[r * ZPITCH + jc]           = acc[ms][nf][0];
            Zs[r * ZPITCH + jc + 1]       = acc[ms][nf][1];
            Zs[(r + 8) * ZPITCH + jc]     = acc[ms][nf][2];
            Zs[(r + 8) * ZPITCH + jc + 1] = acc[ms][nf][3];
        }
    }
    __syncthreads();

    if (tid < 60) {
        int o_l = tid / 3, cv = tid % 3;
        int o_g = tileN * 20 + o_l;
        if (o_g < 100) {
            int cb = o_l * 6;
            float bias = (cv == 0) ? cb1[o_g] : (cv == 1 ? cb2[o_g] : cb3[o_g]);
            float mx = 0.f;
            int k = cv + 1;
            int tmax = min(64 - k, len - k - m0);
            if (cv == 0) {
                for (int t = 0; t <= tmax; t++)
                    mx = fmaxf(mx, Zs[t * ZPITCH + cb] + bias);
            } else if (cv == 1) {
                for (int t = 0; t <= tmax; t++)
                    mx = fmaxf(mx, Zs[t * ZPITCH + cb + 1] + Zs[(t + 1) * ZPITCH + cb + 2] + bias);
            } else {
                for (int t = 0; t <= tmax; t++)
                    mx = fmaxf(mx, Zs[t * ZPITCH + cb + 3] + Zs[(t + 1) * ZPITCH + cb + 4]
                                 + Zs[(t + 2) * ZPITCH + cb + 5] + bias);
            }
            int fidx = b * NCH + side * 300 + cv * 100 + o_g;
            atomicMax((int*)&g_feats[fidx], __float_as_int(mx));
        }
    }
}

// ---------------- dense head ----------------
__global__ void dense_kernel(const float* __restrict__ dw1, const float* __restrict__ db1,
                             const float* __restrict__ dw2, const float* __restrict__ db2,
                             float* __restrict__ out) {
    int b = blockIdx.x;
    __shared__ float f[NCH];
    __shared__ float h[64];
    int tid = threadIdx.x;
    for (int j = tid; j < NCH; j += blockDim.x) f[j] = g_feats[(size_t)b * NCH + j];
    __syncthreads();
    if (tid < 60) {
        float s = db1[tid];
        for (int j = 0; j < NCH; j++) s += f[j] * dw1[j * 60 + tid];
        h[tid] = fmaxf(s, 0.f);
    }
    __syncthreads();
    if (tid < 2) {
        float s = db2[tid];
        for (int j = 0; j < 60; j++) s += h[j] * dw2[j * 2 + tid];
        out[b * 2 + tid] = s;
    }
}

// ---------------- launch ----------------
extern "C" void kernel_launch(void* const* d_in, const int* in_sizes, int n_in,
                              void* d_out, int out_size) {
    const int*   lt   = (const int*)d_in[0];
    const int*   la   = (const int*)d_in[1];
    const int*   ll   = (const int*)d_in[2];
    const int*   rt   = (const int*)d_in[3];
    const int*   ra   = (const int*)d_in[4];
    const int*   rl   = (const int*)d_in[5];
    const float* wemb = (const float*)d_in[6];
    const float* aemb = (const float*)d_in[7];
    const float* cw1  = (const float*)d_in[8];
    const float* cb1  = (const float*)d_in[9];
    const float* cw2  = (const float*)d_in[10];
    const float* cb2  = (const float*)d_in[11];
    const float* cw3  = (const float*)d_in[12];
    const float* cb3  = (const float*)d_in[13];
    const float* dw1  = (const float*)d_in[14];
    const float* db1  = (const float*)d_in[15];
    const float* dw2  = (const float*)d_in[16];
    const float* db2  = (const float*)d_in[17];
    float* out = (float*)d_out;

    const int convSmem = STG_W * 4 * 2;   // 51200 bytes
    const int attSmem  = AST_W * 4 * 2;   // 40960 bytes
    cudaFuncSetAttribute(conv_gemm_kernel,
                         cudaFuncAttributeMaxDynamicSharedMemorySize, convSmem);
    cudaFuncSetAttribute(att_gemm_kernel,
                         cudaFuncAttributeMaxDynamicSharedMemorySize, attSmem);

    init_kernel<<<(BSZ * NCH + 255) / 256, 256>>>(cw1, cw2, cw3);
    gather_kernel<<<dim3(LSZ, BSZ, 2), 96>>>(lt, la, rt, ra, wemb, aemb, ll, rl);
    att_gemm_kernel<<<dim3(3, 3, BSZ), 256, attSmem>>>(ll, rl);
    attproc_kernel<<<dim3((BSZ * LSZ) / 4, 2), 128>>>(ll, rl);
    conv_gemm_kernel<<<dim3(3, 5, 2 * BSZ), 256, convSmem>>>(ll, rl, cb1, cb2, cb3);
    dense_kernel<<<BSZ, 128>>>(dw1, db1, dw2, db2, out);
}

// round 12
// speedup vs baseline: 1.1181x; 1.0496x over previous
#include <cuda_runtime.h>
#include <cuda_bf16.h>
#include <cuda_fp16.h>
#include <math.h>
#include <stdint.h>

// ---------------- problem constants ----------------
#define BSZ   512
#define LSZ   160
#define DDIM  350
#define DP    352     // padded D
#define DPW   176     // DP/2 packed words
#define NCH   600
#define NPAD  640
#define CWP   20      // smem word pitch (16 + 4 pad)
#define ZPITCH 132    // conv Z smem pitch

// ---------------- device scratch ----------------
__device__ unsigned g_lvh [(size_t)BSZ * LSZ * DPW];   // l_vec split hi (bf16x2)
__device__ unsigned g_lvl [(size_t)BSZ * LSZ * DPW];   // l_vec split lo
__device__ unsigned g_rvh [(size_t)BSZ * LSZ * DPW];
__device__ unsigned g_rvl [(size_t)BSZ * LSZ * DPW];
__device__ float    g_att [(size_t)BSZ * LSZ * LSZ];
__device__ float    g_attT[(size_t)BSZ * LSZ * LSZ];
__device__ unsigned g_lcx [(size_t)BSZ * LSZ * DPW];   // l_c as half2
__device__ unsigned g_rcx [(size_t)BSZ * LSZ * DPW];   // r_c as half2
__device__ unsigned g_wallh[(size_t)NPAD * DPW];       // wall fp16 hi (half2)
__device__ unsigned g_walll[(size_t)NPAD * DPW];       // wall fp16 lo (half2)
__device__ float    g_feats[(size_t)BSZ * NCH];

// ---------------- split helpers ----------------
__device__ __forceinline__ void split2(float a, float b, unsigned& hi, unsigned& lo) {
    __nv_bfloat162 h = __floats2bfloat162_rn(a, b);
    float ra = a - __bfloat162float(h.x);
    float rb = b - __bfloat162float(h.y);
    __nv_bfloat162 l = __floats2bfloat162_rn(ra, rb);
    hi = *(unsigned*)&h;
    lo = *(unsigned*)&l;
}
__device__ __forceinline__ void split2h(float a, float b, unsigned& hi, unsigned& lo) {
    __half2 h = __floats2half2_rn(a, b);
    float ra = a - __half2float(__low2half(h));
    float rb = b - __half2float(__high2half(h));
    __half2 l = __floats2half2_rn(ra, rb);
    hi = *(unsigned*)&h;
    lo = *(unsigned*)&l;
}
__device__ __forceinline__ float2 rec2(unsigned h, unsigned l) {
    // bf16 -> f32 is a pure bit placement: hi half in top 16 bits
    float2 r;
    r.x = __uint_as_float(h << 16) + __uint_as_float(l << 16);
    r.y = __uint_as_float(h & 0xFFFF0000u) + __uint_as_float(l & 0xFFFF0000u);
    return r;
}
__device__ __forceinline__ void mma16(float* c, const unsigned* a, unsigned b0, unsigned b1) {
    asm volatile(
        "mma.sync.aligned.m16n8k16.row.col.f32.bf16.bf16.f32 "
        "{%0,%1,%2,%3}, {%4,%5,%6,%7}, {%8,%9}, {%0,%1,%2,%3};"
        : "+f"(c[0]), "+f"(c[1]), "+f"(c[2]), "+f"(c[3])
        : "r"(a[0]), "r"(a[1]), "r"(a[2]), "r"(a[3]), "r"(b0), "r"(b1));
}
__device__ __forceinline__ void mma16h(float* c, const unsigned* a, unsigned b0, unsigned b1) {
    asm volatile(
        "mma.sync.aligned.m16n8k16.row.col.f32.f16.f16.f32 "
        "{%0,%1,%2,%3}, {%4,%5,%6,%7}, {%8,%9}, {%0,%1,%2,%3};"
        : "+f"(c[0]), "+f"(c[1]), "+f"(c[2]), "+f"(c[3])
        : "r"(a[0]), "r"(a[1]), "r"(a[2]), "r"(a[3]), "r"(b0), "r"(b1));
}
__device__ __forceinline__ void ldx4(unsigned* r, unsigned addr) {
    asm volatile("ldmatrix.sync.aligned.m8n8.x4.shared.b16 {%0,%1,%2,%3}, [%4];"
                 : "=r"(r[0]), "=r"(r[1]), "=r"(r[2]), "=r"(r[3]) : "r"(addr));
}
__device__ __forceinline__ void cp16(unsigned dst, const void* src, bool pred) {
    int sz = pred ? 16 : 0;
    asm volatile("cp.async.ca.shared.global [%0], [%1], 16, %2;"
                 :: "r"(dst), "l"(src), "r"(sz));
}
__device__ __forceinline__ void cpcommit() { asm volatile("cp.async.commit_group;"); }
template<int N> __device__ __forceinline__ void cpwait() {
    asm volatile("cp.async.wait_group %0;" :: "n"(N));
}

// ---------------- merged init: zero feats + build permuted fp16-split wall ------
__global__ void init_kernel(const float* __restrict__ w1,
                            const float* __restrict__ w2,
                            const float* __restrict__ w3) {
    int idx = blockIdx.x * blockDim.x + threadIdx.x;
    if (idx < BSZ * NCH) g_feats[idx] = 0.f;
    if (idx < NPAD * DPW) {
        int nn = idx / DPW, p = idx % DPW;
        int tile = nn >> 7, j = nn & 127;
        int o = tile * 20 + j / 6;
        int g = j % 6;
        bool valid = (j < 120) && (o < 100);
        float v[2];
#pragma unroll
        for (int c = 0; c < 2; c++) {
            int k = 2 * p + c;
            float x = 0.f;
            if (valid && k < DDIM) {
                if      (g == 0) x = w1[o * DDIM + k];
                else if (g <= 2) x = w2[o * (DDIM * 2) + k * 2 + (g - 1)];
                else             x = w3[o * (DDIM * 3) + k * 3 + (g - 3)];
            }
            v[c] = x;
        }
        unsigned hi, lo;
        split2h(v[0], v[1], hi, lo);
        g_wallh[idx] = hi;
        g_walll[idx] = lo;
    }
}

// ---------------- embedding gather v2: float2 loads, uint2 stores, 2 rows/block -
__global__ void gather_kernel(const int* __restrict__ lt, const int* __restrict__ la,
                              const int* __restrict__ rt, const int* __restrict__ ra,
                              const float* __restrict__ wemb, const float* __restrict__ aemb,
                              const int* __restrict__ ll, const int* __restrict__ rl) {
    int sub = threadIdx.x / 96;              // 0..1  (row within block)
    int q   = threadIdx.x % 96;
    int l = blockIdx.x * 2 + sub;
    int b = blockIdx.y, side = blockIdx.z;
    int len = side ? rl[b] : ll[b];
    if (l >= len) return;                    // rows >= len never read downstream
    const int* tok = side ? rt : lt;
    const int* atr = side ? ra : la;
    size_t rowo = ((size_t)(b * LSZ + l)) * DPW;
    unsigned* dstH = (side ? g_rvh : g_lvh) + rowo;
    unsigned* dstL = (side ? g_rvl : g_lvl) + rowo;
    int t = tok[l * BSZ + b];
    int a = atr[l * BSZ + b];
    const float* wr = wemb + (size_t)t * 300;
    const float* ar = aemb + (size_t)a * 50;
    if (q < 88) {
        int d0 = q * 4;
        float v0, v1, v2, v3;
        if (d0 + 3 < 50) {                       // q <= 11: pure attr, 8B-aligned
            float2 p0 = *(const float2*)(ar + d0);
            float2 p1 = *(const float2*)(ar + d0 + 2);
            v0 = p0.x; v1 = p0.y; v2 = p1.x; v3 = p1.y;
        } else if (d0 >= 52 && d0 + 3 < DDIM) {  // q in [13,86]: pure word, 8B-aligned
            const float* wp = wr + (d0 - 50);
            float2 p0 = *(const float2*)(wp);
            float2 p1 = *(const float2*)(wp + 2);
            v0 = p0.x; v1 = p0.y; v2 = p1.x; v3 = p1.y;
        } else if (d0 == 48) {                   // q == 12: 2 attr + 2 word
            float2 p0 = *(const float2*)(ar + 48);
            float2 p1 = *(const float2*)(wr);
            v0 = p0.x; v1 = p0.y; v2 = p1.x; v3 = p1.y;
        } else {                                  // q == 87 (d0=348): 2 word + 2 zero
            float2 p0 = *(const float2*)(wr + 298);
            v0 = p0.x; v1 = p0.y; v2 = 0.f; v3 = 0.f;
        }
        unsigned h0, l0, h1, l1;
        split2(v0, v1, h0, l0);
        split2(v2, v3, h1, l1);
        *(uint2*)(dstH + q * 2) = make_uint2(h0, h1);
        *(uint2*)(dstL + q * 2) = make_uint2(l0, l1);
    }
}

// =====================================================================
// att GEMM (round-9 proven): 64x64 tile, 8 warps (2m x 4n, 32x16 warp
// tiles), cp.async 2-stage + ldmatrix, bf16 3-term split.
// =====================================================================
#define AST_AH 0
#define AST_AL (64 * CWP)
#define AST_BH (2 * 64 * CWP)
#define AST_BL (3 * 64 * CWP)
#define AST_W  (4 * 64 * CWP)
#define NKB    11

__global__ __launch_bounds__(256) void att_gemm_kernel(const int* __restrict__ llen,
                                                       const int* __restrict__ rlen) {
    extern __shared__ unsigned asw[];
    int b  = blockIdx.z;
    int m0 = blockIdx.x * 64;
    int n0 = blockIdx.y * 64;
    if (m0 >= llen[b] || n0 >= rlen[b]) return;

    const unsigned* Avh = g_lvh + (size_t)b * LSZ * DPW;
    const unsigned* Avl = g_lvl + (size_t)b * LSZ * DPW;
    const unsigned* Bvh = g_rvh + (size_t)b * LSZ * DPW;
    const unsigned* Bvl = g_rvl + (size_t)b * LSZ * DPW;

    int tid  = threadIdx.x;
    int lane = tid & 31;
    int wid  = tid >> 5;
    int wm   = wid & 1;
    int wn   = wid >> 1;

    unsigned sbase = (unsigned)__cvta_generic_to_shared(asw);

    int ar = tid >> 2, ac = tid & 3;
    bool aok = (m0 + ar) < LSZ;
    bool bok = (n0 + ar) < LSZ;
    const unsigned* asH = Avh + (size_t)(aok ? m0 + ar : 0) * DPW + ac * 4;
    const unsigned* asL = Avl + (size_t)(aok ? m0 + ar : 0) * DPW + ac * 4;
    const unsigned* bsH = Bvh + (size_t)(bok ? n0 + ar : 0) * DPW + ac * 4;
    const unsigned* bsL = Bvl + (size_t)(bok ? n0 + ar : 0) * DPW + ac * 4;
    unsigned dA = (ar * CWP + ac * 4);

    float acc[2][2][4];
#pragma unroll
    for (int ms = 0; ms < 2; ms++)
#pragma unroll
        for (int nf = 0; nf < 2; nf++)
#pragma unroll
            for (int q = 0; q < 4; q++) acc[ms][nf][q] = 0.f;

#define ACOPY(kb, s) do {                                                \
    unsigned sb0 = sbase + (s) * (AST_W * 4);                            \
    cp16(sb0 + (AST_AH + dA) * 4, asH + (kb) * 16, aok);                 \
    cp16(sb0 + (AST_AL + dA) * 4, asL + (kb) * 16, aok);                 \
    cp16(sb0 + (AST_BH + dA) * 4, bsH + (kb) * 16, bok);                 \
    cp16(sb0 + (AST_BL + dA) * 4, bsL + (kb) * 16, bok);                 \
} while (0)

    ACOPY(0, 0);
    cpcommit();

    for (int kb = 0; kb < NKB; kb++) {
        if (kb + 1 < NKB) {
            ACOPY(kb + 1, (kb + 1) & 1);
            cpcommit();
            cpwait<1>();
        } else {
            cpwait<0>();
        }
        __syncthreads();

        unsigned sb0 = sbase + (kb & 1) * (AST_W * 4);
#pragma unroll
        for (int ks = 0; ks < 2; ks++) {
            unsigned ahf[2][4], alf[2][4];
#pragma unroll
            for (int ms = 0; ms < 2; ms++) {
                int r = wm * 32 + ms * 16 + (lane & 7) + ((lane >> 3) & 1) * 8;
                int c = ks * 2 + (lane >> 4);
                ldx4(ahf[ms], sb0 + (AST_AH + r * CWP + c * 4) * 4);
                ldx4(alf[ms], sb0 + (AST_AL + r * CWP + c * 4) * 4);
            }
            int rB = wn * 16 + ((lane >> 4) & 1) * 8 + (lane & 7);
            int cB = ks * 2 + ((lane >> 3) & 1);
            unsigned bh[4], bl[4];
            ldx4(bh, sb0 + (AST_BH + rB * CWP + cB * 4) * 4);
            ldx4(bl, sb0 + (AST_BL + rB * CWP + cB * 4) * 4);
#pragma unroll
            for (int ms = 0; ms < 2; ms++) {
                mma16(acc[ms][0], ahf[ms], bh[0], bh[1]);
                mma16(acc[ms][0], ahf[ms], bl[0], bl[1]);
                mma16(acc[ms][0], alf[ms], bh[0], bh[1]);
                mma16(acc[ms][1], ahf[ms], bh[2], bh[3]);
                mma16(acc[ms][1], ahf[ms], bl[2], bl[3]);
                mma16(acc[ms][1], alf[ms], bh[2], bh[3]);
            }
        }
        __syncthreads();
    }
#undef ACOPY

    float* Ts = (float*)asw;
#pragma unroll
    for (int ms = 0; ms < 2; ms++) {
        int r = wm * 32 + ms * 16 + (lane >> 2);
#pragma unroll
        for (int nf = 0; nf < 2; nf++) {
            int cn = wn * 16 + nf * 8 + 2 * (lane & 3);
            Ts[r * 68 + cn]           = acc[ms][nf][0];
            Ts[r * 68 + cn + 1]       = acc[ms][nf][1];
            Ts[(r + 8) * 68 + cn]     = acc[ms][nf][2];
            Ts[(r + 8) * 68 + cn + 1] = acc[ms][nf][3];
        }
    }
    __syncthreads();

    {
        int row = tid >> 2;
        int gm = m0 + row;
        if (gm < LSZ) {
#pragma unroll
            for (int q = 0; q < 4; q++) {
                int cl = (tid & 3) * 16 + q * 4;
                int gn = n0 + cl;
                if (gn < LSZ)
                    *(float4*)(g_att + ((size_t)b * LSZ + gm) * LSZ + gn) =
                        *(const float4*)&Ts[row * 68 + cl];
            }
        }
    }
    {
        int rr = tid >> 2;
        int gr = n0 + rr;
        if (gr < LSZ) {
#pragma unroll
            for (int q = 0; q < 4; q++) {
                int l0 = (tid & 3) * 16 + q * 4;
                int gl = m0 + l0;
                if (gl < LSZ) {
                    float4 o;
                    o.x = Ts[(l0 + 0) * 68 + rr];
                    o.y = Ts[(l0 + 1) * 68 + rr];
                    o.z = Ts[(l0 + 2) * 68 + rr];
                    o.w = Ts[(l0 + 3) * 68 + rr];
                    *(float4*)(g_attT + ((size_t)b * LSZ + gr) * LSZ + gl) = o;
                }
            }
        }
    }
}

// ---------------- fused softmax / stats / top-3 / counterpart ----------------
__device__ __forceinline__ bool tk_better(float av, int ai, float bv, int bi) {
    return (av > bv) || (av == bv && ai < bi);
}
__device__ __forceinline__ void tk_insert(float nv, int ni,
                                          float& v0, int& i0, float& v1, int& i1, float& v2, int& i2) {
    if (tk_better(nv, ni, v0, i0)) { v2 = v1; i2 = i1; v1 = v0; i1 = i0; v0 = nv; i0 = ni; }
    else if (tk_better(nv, ni, v1, i1)) { v2 = v1; i2 = i1; v1 = nv; i1 = ni; }
    else if (tk_better(nv, ni, v2, i2)) { v2 = nv; i2 = ni; }
}

__global__ void attproc_kernel(const int* __restrict__ ll, const int* __restrict__ rl) {
    int side = blockIdx.y;
    const float* attRows   = side ? g_attT : g_att;
    const unsigned* selfH  = side ? g_rvh : g_lvh;
    const unsigned* selfL  = side ? g_rvl : g_lvl;
    const unsigned* othH   = side ? g_lvh : g_rvh;
    const unsigned* othL   = side ? g_lvl : g_rvl;
    const int* lenSelf     = side ? rl : ll;
    const int* lenOther    = side ? ll : rl;
    unsigned* outX         = side ? g_rcx : g_lcx;

    int wid  = blockIdx.x * (blockDim.x >> 5) + (threadIdx.x >> 5);
    int lane = threadIdx.x & 31;
    int b = wid / LSZ, i = wid % LSZ;
    if (b >= BSZ) return;
    if (i >= lenSelf[b]) return;
    int n = lenOther[b];
    const float* row = attRows + ((size_t)b * LSZ + i) * LSZ;
    const unsigned FULL = 0xffffffffu;

    float rv[5];
#pragma unroll
    for (int k = 0; k < 5; k++) {
        int j = lane + 32 * k;
        rv[k] = (j < n) ? row[j] : -3.0e38f;
    }

    float v0 = -3.0e38f, v1 = -3.0e38f, v2 = -3.0e38f;
    int i0 = 0x7fffffff, i1 = 0x7fffffff, i2 = 0x7fffffff;
#pragma unroll
    for (int k = 0; k < 5; k++) {
        int j = lane + 32 * k;
        if (j < n) tk_insert(rv[k], j, v0, i0, v1, i1, v2, i2);
    }
#pragma unroll
    for (int off = 16; off >= 1; off >>= 1) {
        float ov0 = __shfl_xor_sync(FULL, v0, off);
        int   oi0 = __shfl_xor_sync(FULL, i0, off);
        float ov1 = __shfl_xor_sync(FULL, v1, off);
        int   oi1 = __shfl_xor_sync(FULL, i1, off);
        float ov2 = __shfl_xor_sync(FULL, v2, off);
        int   oi2 = __shfl_xor_sync(FULL, i2, off);
        tk_insert(ov0, oi0, v0, i0, v1, i1, v2, i2);
        tk_insert(ov1, oi1, v0, i0, v1, i1, v2, i2);
        tk_insert(ov2, oi2, v0, i0, v1, i1, v2, i2);
    }
    float m = v0;

    float S = 0.f, S2 = 0.f;
#pragma unroll
    for (int k = 0; k < 5; k++) {
        int j = lane + 32 * k;
        if (j < n) {
            float e = __expf(rv[k] - m);
            S += e; S2 += e * e;
        }
    }
#pragma unroll
    for (int off = 16; off >= 1; off >>= 1) {
        S  += __shfl_xor_sync(FULL, S,  off);
        S2 += __shfl_xor_sync(FULL, S2, off);
    }

    float rlenf = (float)n;
    float mean  = 1.0f / rlenf;
    float s2    = S2 / (S * S);
    float w     = (s2 / rlenf - mean * mean) / fmaxf(mean, 0.001f);

    float a0 = 1.0f, a1 = __expf(v1 - v0), a2 = __expf(v2 - v0);
    float inv = __fdividef(1.0f, a0 + a1 + a2);
    a0 *= inv; a1 *= inv; a2 *= inv;

    size_t r0 = ((size_t)b * LSZ + i0) * DPW;
    size_t r1 = ((size_t)b * LSZ + i1) * DPW;
    size_t r2 = ((size_t)b * LSZ + i2) * DPW;
    size_t rs = ((size_t)b * LSZ + i) * DPW;

#pragma unroll
    for (int k = 0; k < 6; k++) {
        int p = lane + 32 * k;
        if (p < DPW) {
            float x0 = 0.f, x1 = 0.f;
            if (p < 175) {
                float2 e0 = rec2(othH[r0 + p], othL[r0 + p]);
                float2 e1 = rec2(othH[r1 + p], othL[r1 + p]);
                float2 e2 = rec2(othH[r2 + p], othL[r2 + p]);
                float2 s  = rec2(selfH[rs + p], selfL[rs + p]);
                float c0 = a0 * e0.x + a1 * e1.x + a2 * e2.x;
                float c1 = a0 * e0.y + a1 * e1.y + a2 * e2.y;
                x0 = w * fabsf(s.x - c0);
                x1 = w * fabsf(s.y - c1);
            }
            __half2 hx = __floats2half2_rn(x0, x1);
            outX[rs + p] = *(unsigned*)&hx;
        }
    }
}

// =====================================================================
// conv GEMM fused with relu-max pooling (round-9 proven, unchanged)
// =====================================================================
#define STG_W  (64 * CWP + 128 * CWP + 128 * CWP)
#define OFF_A  0
#define OFF_BH (64 * CWP)
#define OFF_BL (64 * CWP + 128 * CWP)

__global__ __launch_bounds__(256) void conv_gemm_kernel(const int* __restrict__ llen,
                                                        const int* __restrict__ rlen,
                                                        const float* __restrict__ cb1,
                                                        const float* __restrict__ cb2,
                                                        const float* __restrict__ cb3) {
    extern __shared__ unsigned smw[];
    int zb = blockIdx.z;
    int side = zb >> 9, b = zb & 511;
    int m0 = blockIdx.x * 62;          // overlapped m-tiles: 0, 62, 124
    int tileN = blockIdx.y;            // 0..4
    int len = side ? rlen[b] : llen[b];
    if (m0 >= len) return;

    const unsigned* Ax = (side ? g_rcx : g_lcx) + (size_t)b * LSZ * DPW;
    int n0 = tileN * 128;

    int tid  = threadIdx.x;
    int lane = tid & 31;
    int wid  = tid >> 5;
    int wm   = wid & 1;
    int wn   = wid >> 1;

    unsigned sbase = (unsigned)__cvta_generic_to_shared(smw);

    int ar = tid >> 2, ac = tid & 3;
    int agm = m0 + ar;
    bool aok = agm < LSZ;
    const unsigned* asrc = Ax + (size_t)(aok ? agm : 0) * DPW + ac * 4;
    unsigned adst = (OFF_A + ar * CWP + ac * 4);

    float acc[2][4][4];
#pragma unroll
    for (int ms = 0; ms < 2; ms++)
#pragma unroll
        for (int nf = 0; nf < 4; nf++)
#pragma unroll
            for (int q = 0; q < 4; q++) acc[ms][nf][q] = 0.f;

#define COPY_STAGE(kb, s) do {                                                    \
    unsigned sb0 = sbase + (s) * (STG_W * 4);                                     \
    cp16(sb0 + adst * 4, asrc + (kb) * 16, aok);                                  \
    _Pragma("unroll")                                                             \
    for (int q = 0; q < 2; q++) {                                                 \
        int cid = tid + 256 * q;                                                  \
        int br = cid >> 2, bc = cid & 3;                                          \
        cp16(sb0 + (OFF_BH + br * CWP + bc * 4) * 4,                              \
             g_wallh + (size_t)(n0 + br) * DPW + (kb) * 16 + bc * 4, true);       \
        cp16(sb0 + (OFF_BL + br * CWP + bc * 4) * 4,                              \
             g_walll + (size_t)(n0 + br) * DPW + (kb) * 16 + bc * 4, true);       \
    }                                                                             \
} while (0)

    COPY_STAGE(0, 0);
    cpcommit();

    for (int kb = 0; kb < NKB; kb++) {
        if (kb + 1 < NKB) {
            COPY_STAGE(kb + 1, (kb + 1) & 1);
            cpcommit();
            cpwait<1>();
        } else {
            cpwait<0>();
        }
        __syncthreads();

        unsigned sb0 = sbase + (kb & 1) * (STG_W * 4);
#pragma unroll
        for (int ks = 0; ks < 2; ks++) {
            unsigned af[2][4];
#pragma unroll
            for (int ms = 0; ms < 2; ms++) {
                int r = wm * 32 + ms * 16 + (lane & 7) + ((lane >> 3) & 1) * 8;
                int c = ks * 2 + (lane >> 4);
                ldx4(af[ms], sb0 + (OFF_A + r * CWP + c * 4) * 4);
            }
#pragma unroll
            for (int nfp = 0; nfp < 2; nfp++) {
                int rB = wn * 32 + nfp * 16 + ((lane >> 4) & 1) * 8 + (lane & 7);
                int cB = ks * 2 + ((lane >> 3) & 1);
                unsigned bh[4], bl[4];
                ldx4(bh, sb0 + (OFF_BH + rB * CWP + cB * 4) * 4);
                ldx4(bl, sb0 + (OFF_BL + rB * CWP + cB * 4) * 4);
#pragma unroll
                for (int ms = 0; ms < 2; ms++) {
                    mma16h(acc[ms][2 * nfp],     af[ms], bh[0], bh[1]);
                    mma16h(acc[ms][2 * nfp],     af[ms], bl[0], bl[1]);
                    mma16h(acc[ms][2 * nfp + 1], af[ms], bh[2], bh[3]);
                    mma16h(acc[ms][2 * nfp + 1], af[ms], bl[2], bl[3]);
                }
            }
        }
        __syncthreads();
    }
#undef COPY_STAGE

    float* Zs = (float*)smw;          // [64][ZPITCH]
#pragma unroll
    for (int ms = 0; ms < 2; ms++) {
        int r = wm * 32 + ms * 16 + (lane >> 2);
#pragma unroll
        for (int nf = 0; nf < 4; nf++) {
            int jc = wn * 32 + nf * 8 + 2 * (lane & 3);
            Zs[r * ZPITCH + jc]           = acc[ms][nf][0];
            Zs[r * ZPITCH + jc + 1]       = acc[ms][nf][1];
            Zs[(r + 8) * ZPITCH + jc]     = acc[ms][nf][2];
            Zs[(r + 8) * ZPITCH + jc + 1] = acc[ms][nf][3];
        }
    }
    __syncthreads();

    if (tid < 60) {
        int o_l = tid / 3, cv = tid % 3;
        int o_g = tileN * 20 + o_l;
        if (o_g < 100) {
            int cb = o_l * 6;
            float bias = (cv == 0) ? cb1[o_g] : (cv == 1 ? cb2[o_g] : cb3[o_g]);
            float mx = 0.f;
            int k = cv + 1;
            int tmax = min(64 - k, len - k - m0);
            if (cv == 0) {
                for (int t = 0; t <= tmax; t++)
                    mx = fmaxf(mx, Zs[t * ZPITCH + cb] + bias);
            } else if (cv == 1) {
                for (int t = 0; t <= tmax; t++)
                    mx = fmaxf(mx, Zs[t * ZPITCH + cb + 1] + Zs[(t + 1) * ZPITCH + cb + 2] + bias);
            } else {
                for (int t = 0; t <= tmax; t++)
                    mx = fmaxf(mx, Zs[t * ZPITCH + cb + 3] + Zs[(t + 1) * ZPITCH + cb + 4]
                                 + Zs[(t + 2) * ZPITCH + cb + 5] + bias);
            }
            int fidx = b * NCH + side * 300 + cv * 100 + o_g;
            atomicMax((int*)&g_feats[fidx], __float_as_int(mx));
        }
    }
}

// ---------------- dense head ----------------
__global__ void dense_kernel(const float* __restrict__ dw1, const float* __restrict__ db1,
                             const float* __restrict__ dw2, const float* __restrict__ db2,
                             float* __restrict__ out) {
    int b = blockIdx.x;
    __shared__ float f[NCH];
    __shared__ float h[64];
    int tid = threadIdx.x;
    for (int j = tid; j < NCH; j += blockDim.x) f[j] = g_feats[(size_t)b * NCH + j];
    __syncthreads();
    if (tid < 60) {
        float s = db1[tid];
        for (int j = 0; j < NCH; j++) s += f[j] * dw1[j * 60 + tid];
        h[tid] = fmaxf(s, 0.f);
    }
    __syncthreads();
    if (tid < 2) {
        float s = db2[tid];
        for (int j = 0; j < 60; j++) s += h[j] * dw2[j * 2 + tid];
        out[b * 2 + tid] = s;
    }
}

// ---------------- launch ----------------
extern "C" void kernel_launch(void* const* d_in, const int* in_sizes, int n_in,
                              void* d_out, int out_size) {
    const int*   lt   = (const int*)d_in[0];
    const int*   la   = (const int*)d_in[1];
    const int*   ll   = (const int*)d_in[2];
    const int*   rt   = (const int*)d_in[3];
    const int*   ra   = (const int*)d_in[4];
    const int*   rl   = (const int*)d_in[5];
    const float* wemb = (const float*)d_in[6];
    const float* aemb = (const float*)d_in[7];
    const float* cw1  = (const float*)d_in[8];
    const float* cb1  = (const float*)d_in[9];
    const float* cw2  = (const float*)d_in[10];
    const float* cb2  = (const float*)d_in[11];
    const float* cw3  = (const float*)d_in[12];
    const float* cb3  = (const float*)d_in[13];
    const float* dw1  = (const float*)d_in[14];
    const float* db1  = (const float*)d_in[15];
    const float* dw2  = (const float*)d_in[16];
    const float* db2  = (const float*)d_in[17];
    float* out = (float*)d_out;

    const int convSmem = STG_W * 4 * 2;   // 51200 bytes
    const int attSmem  = AST_W * 4 * 2;   // 40960 bytes
    cudaFuncSetAttribute(conv_gemm_kernel,
                         cudaFuncAttributeMaxDynamicSharedMemorySize, convSmem);
    cudaFuncSetAttribute(att_gemm_kernel,
                         cudaFuncAttributeMaxDynamicSharedMemorySize, attSmem);

    init_kernel<<<(BSZ * NCH + 255) / 256, 256>>>(cw1, cw2, cw3);
    gather_kernel<<<dim3(LSZ / 2, BSZ, 2), 192>>>(lt, la, rt, ra, wemb, aemb, ll, rl);
    att_gemm_kernel<<<dim3(3, 3, BSZ), 256, attSmem>>>(ll, rl);
    attproc_kernel<<<dim3((BSZ * LSZ) / 4, 2), 128>>>(ll, rl);
    conv_gemm_kernel<<<dim3(3, 5, 2 * BSZ), 256, convSmem>>>(ll, rl, cb1, cb2, cb3);
    dense_kernel<<<BSZ, 128>>>(dw1, db1, dw2, db2, out);
}

// round 13
// speedup vs baseline: 1.3194x; 1.1800x over previous
#include <cuda_runtime.h>
#include <cuda_bf16.h>
#include <cuda_fp16.h>
#include <math.h>
#include <stdint.h>

// ---------------- problem constants ----------------
#define BSZ   512
#define LSZ   160
#define DDIM  350
#define DP    352     // padded D
#define DPW   176     // DP/2 packed words
#define NCH   600
#define NPAD  640
#define CWP   20      // smem word pitch (16 + 4 pad)
#define ZP2   129     // conv Z smem pitch (128 rows)

// ---------------- device scratch ----------------
__device__ unsigned g_lvh [(size_t)BSZ * LSZ * DPW];   // l_vec split hi (bf16x2)
__device__ unsigned g_lvl [(size_t)BSZ * LSZ * DPW];   // l_vec split lo
__device__ unsigned g_rvh [(size_t)BSZ * LSZ * DPW];
__device__ unsigned g_rvl [(size_t)BSZ * LSZ * DPW];
__device__ float    g_att [(size_t)BSZ * LSZ * LSZ];
__device__ float    g_attT[(size_t)BSZ * LSZ * LSZ];
__device__ unsigned g_lcx [(size_t)BSZ * LSZ * DPW];   // l_c as half2
__device__ unsigned g_rcx [(size_t)BSZ * LSZ * DPW];   // r_c as half2
__device__ unsigned g_wallh[(size_t)NPAD * DPW];       // wall fp16 (half2)
__device__ float    g_feats[(size_t)BSZ * NCH];

// ---------------- split helpers ----------------
__device__ __forceinline__ void split2(float a, float b, unsigned& hi, unsigned& lo) {
    __nv_bfloat162 h = __floats2bfloat162_rn(a, b);
    float ra = a - __bfloat162float(h.x);
    float rb = b - __bfloat162float(h.y);
    __nv_bfloat162 l = __floats2bfloat162_rn(ra, rb);
    hi = *(unsigned*)&h;
    lo = *(unsigned*)&l;
}
__device__ __forceinline__ float2 rec2(unsigned h, unsigned l) {
    float2 r;
    r.x = __uint_as_float(h << 16) + __uint_as_float(l << 16);
    r.y = __uint_as_float(h & 0xFFFF0000u) + __uint_as_float(l & 0xFFFF0000u);
    return r;
}
__device__ __forceinline__ void mma16(float* c, const unsigned* a, unsigned b0, unsigned b1) {
    asm volatile(
        "mma.sync.aligned.m16n8k16.row.col.f32.bf16.bf16.f32 "
        "{%0,%1,%2,%3}, {%4,%5,%6,%7}, {%8,%9}, {%0,%1,%2,%3};"
        : "+f"(c[0]), "+f"(c[1]), "+f"(c[2]), "+f"(c[3])
        : "r"(a[0]), "r"(a[1]), "r"(a[2]), "r"(a[3]), "r"(b0), "r"(b1));
}
__device__ __forceinline__ void mma16h(float* c, const unsigned* a, unsigned b0, unsigned b1) {
    asm volatile(
        "mma.sync.aligned.m16n8k16.row.col.f32.f16.f16.f32 "
        "{%0,%1,%2,%3}, {%4,%5,%6,%7}, {%8,%9}, {%0,%1,%2,%3};"
        : "+f"(c[0]), "+f"(c[1]), "+f"(c[2]), "+f"(c[3])
        : "r"(a[0]), "r"(a[1]), "r"(a[2]), "r"(a[3]), "r"(b0), "r"(b1));
}
__device__ __forceinline__ void ldx4(unsigned* r, unsigned addr) {
    asm volatile("ldmatrix.sync.aligned.m8n8.x4.shared.b16 {%0,%1,%2,%3}, [%4];"
                 : "=r"(r[0]), "=r"(r[1]), "=r"(r[2]), "=r"(r[3]) : "r"(addr));
}
__device__ __forceinline__ void cp16(unsigned dst, const void* src, bool pred) {
    int sz = pred ? 16 : 0;
    asm volatile("cp.async.ca.shared.global [%0], [%1], 16, %2;"
                 :: "r"(dst), "l"(src), "r"(sz));
}
__device__ __forceinline__ void cpcommit() { asm volatile("cp.async.commit_group;"); }
template<int N> __device__ __forceinline__ void cpwait() {
    asm volatile("cp.async.wait_group %0;" :: "n"(N));
}

// ---------------- merged init: zero feats + build permuted fp16 wall ------------
__global__ void init_kernel(const float* __restrict__ w1,
                            const float* __restrict__ w2,
                            const float* __restrict__ w3) {
    int idx = blockIdx.x * blockDim.x + threadIdx.x;
    if (idx < BSZ * NCH) g_feats[idx] = 0.f;
    if (idx < NPAD * DPW) {
        int nn = idx / DPW, p = idx % DPW;
        int tile = nn >> 7, j = nn & 127;
        int o = tile * 20 + j / 6;
        int g = j % 6;
        bool valid = (j < 120) && (o < 100);
        float v[2];
#pragma unroll
        for (int c = 0; c < 2; c++) {
            int k = 2 * p + c;
            float x = 0.f;
            if (valid && k < DDIM) {
                if      (g == 0) x = w1[o * DDIM + k];
                else if (g <= 2) x = w2[o * (DDIM * 2) + k * 2 + (g - 1)];
                else             x = w3[o * (DDIM * 3) + k * 3 + (g - 3)];
            }
            v[c] = x;
        }
        __half2 h = __floats2half2_rn(v[0], v[1]);
        g_wallh[idx] = *(unsigned*)&h;
    }
}

// ---------------- embedding gather v2 (round-12 proven) ----------------
__global__ void gather_kernel(const int* __restrict__ lt, const int* __restrict__ la,
                              const int* __restrict__ rt, const int* __restrict__ ra,
                              const float* __restrict__ wemb, const float* __restrict__ aemb,
                              const int* __restrict__ ll, const int* __restrict__ rl) {
    int sub = threadIdx.x / 96;
    int q   = threadIdx.x % 96;
    int l = blockIdx.x * 2 + sub;
    int b = blockIdx.y, side = blockIdx.z;
    int len = side ? rl[b] : ll[b];
    if (l >= len) return;
    const int* tok = side ? rt : lt;
    const int* atr = side ? ra : la;
    size_t rowo = ((size_t)(b * LSZ + l)) * DPW;
    unsigned* dstH = (side ? g_rvh : g_lvh) + rowo;
    unsigned* dstL = (side ? g_rvl : g_lvl) + rowo;
    int t = tok[l * BSZ + b];
    int a = atr[l * BSZ + b];
    const float* wr = wemb + (size_t)t * 300;
    const float* ar = aemb + (size_t)a * 50;
    if (q < 88) {
        int d0 = q * 4;
        float v0, v1, v2, v3;
        if (d0 + 3 < 50) {
            float2 p0 = *(const float2*)(ar + d0);
            float2 p1 = *(const float2*)(ar + d0 + 2);
            v0 = p0.x; v1 = p0.y; v2 = p1.x; v3 = p1.y;
        } else if (d0 >= 52 && d0 + 3 < DDIM) {
            const float* wp = wr + (d0 - 50);
            float2 p0 = *(const float2*)(wp);
            float2 p1 = *(const float2*)(wp + 2);
            v0 = p0.x; v1 = p0.y; v2 = p1.x; v3 = p1.y;
        } else if (d0 == 48) {
            float2 p0 = *(const float2*)(ar + 48);
            float2 p1 = *(const float2*)(wr);
            v0 = p0.x; v1 = p0.y; v2 = p1.x; v3 = p1.y;
        } else {
            float2 p0 = *(const float2*)(wr + 298);
            v0 = p0.x; v1 = p0.y; v2 = 0.f; v3 = 0.f;
        }
        unsigned h0, l0, h1, l1;
        split2(v0, v1, h0, l0);
        split2(v2, v3, h1, l1);
        *(uint2*)(dstH + q * 2) = make_uint2(h0, h1);
        *(uint2*)(dstL + q * 2) = make_uint2(l0, l1);
    }
}

// =====================================================================
// att GEMM (round-9 proven, unchanged)
// =====================================================================
#define AST_AH 0
#define AST_AL (64 * CWP)
#define AST_BH (2 * 64 * CWP)
#define AST_BL (3 * 64 * CWP)
#define AST_W  (4 * 64 * CWP)
#define NKB    11

__global__ __launch_bounds__(256) void att_gemm_kernel(const int* __restrict__ llen,
                                                       const int* __restrict__ rlen) {
    extern __shared__ unsigned asw[];
    int b  = blockIdx.z;
    int m0 = blockIdx.x * 64;
    int n0 = blockIdx.y * 64;
    if (m0 >= llen[b] || n0 >= rlen[b]) return;

    const unsigned* Avh = g_lvh + (size_t)b * LSZ * DPW;
    const unsigned* Avl = g_lvl + (size_t)b * LSZ * DPW;
    const unsigned* Bvh = g_rvh + (size_t)b * LSZ * DPW;
    const unsigned* Bvl = g_rvl + (size_t)b * LSZ * DPW;

    int tid  = threadIdx.x;
    int lane = tid & 31;
    int wid  = tid >> 5;
    int wm   = wid & 1;
    int wn   = wid >> 1;

    unsigned sbase = (unsigned)__cvta_generic_to_shared(asw);

    int ar = tid >> 2, ac = tid & 3;
    bool aok = (m0 + ar) < LSZ;
    bool bok = (n0 + ar) < LSZ;
    const unsigned* asH = Avh + (size_t)(aok ? m0 + ar : 0) * DPW + ac * 4;
    const unsigned* asL = Avl + (size_t)(aok ? m0 + ar : 0) * DPW + ac * 4;
    const unsigned* bsH = Bvh + (size_t)(bok ? n0 + ar : 0) * DPW + ac * 4;
    const unsigned* bsL = Bvl + (size_t)(bok ? n0 + ar : 0) * DPW + ac * 4;
    unsigned dA = (ar * CWP + ac * 4);

    float acc[2][2][4];
#pragma unroll
    for (int ms = 0; ms < 2; ms++)
#pragma unroll
        for (int nf = 0; nf < 2; nf++)
#pragma unroll
            for (int q = 0; q < 4; q++) acc[ms][nf][q] = 0.f;

#define ACOPY(kb, s) do {                                                \
    unsigned sb0 = sbase + (s) * (AST_W * 4);                            \
    cp16(sb0 + (AST_AH + dA) * 4, asH + (kb) * 16, aok);                 \
    cp16(sb0 + (AST_AL + dA) * 4, asL + (kb) * 16, aok);                 \
    cp16(sb0 + (AST_BH + dA) * 4, bsH + (kb) * 16, bok);                 \
    cp16(sb0 + (AST_BL + dA) * 4, bsL + (kb) * 16, bok);                 \
} while (0)

    ACOPY(0, 0);
    cpcommit();

    for (int kb = 0; kb < NKB; kb++) {
        if (kb + 1 < NKB) {
            ACOPY(kb + 1, (kb + 1) & 1);
            cpcommit();
            cpwait<1>();
        } else {
            cpwait<0>();
        }
        __syncthreads();

        unsigned sb0 = sbase + (kb & 1) * (AST_W * 4);
#pragma unroll
        for (int ks = 0; ks < 2; ks++) {
            unsigned ahf[2][4], alf[2][4];
#pragma unroll
            for (int ms = 0; ms < 2; ms++) {
                int r = wm * 32 + ms * 16 + (lane & 7) + ((lane >> 3) & 1) * 8;
                int c = ks * 2 + (lane >> 4);
                ldx4(ahf[ms], sb0 + (AST_AH + r * CWP + c * 4) * 4);
                ldx4(alf[ms], sb0 + (AST_AL + r * CWP + c * 4) * 4);
            }
            int rB = wn * 16 + ((lane >> 4) & 1) * 8 + (lane & 7);
            int cB = ks * 2 + ((lane >> 3) & 1);
            unsigned bh[4], bl[4];
            ldx4(bh, sb0 + (AST_BH + rB * CWP + cB * 4) * 4);
            ldx4(bl, sb0 + (AST_BL + rB * CWP + cB * 4) * 4);
#pragma unroll
            for (int ms = 0; ms < 2; ms++) {
                mma16(acc[ms][0], ahf[ms], bh[0], bh[1]);
                mma16(acc[ms][0], ahf[ms], bl[0], bl[1]);
                mma16(acc[ms][0], alf[ms], bh[0], bh[1]);
                mma16(acc[ms][1], ahf[ms], bh[2], bh[3]);
                mma16(acc[ms][1], ahf[ms], bl[2], bl[3]);
                mma16(acc[ms][1], alf[ms], bh[2], bh[3]);
            }
        }
        __syncthreads();
    }
#undef ACOPY

    float* Ts = (float*)asw;
#pragma unroll
    for (int ms = 0; ms < 2; ms++) {
        int r = wm * 32 + ms * 16 + (lane >> 2);
#pragma unroll
        for (int nf = 0; nf < 2; nf++) {
            int cn = wn * 16 + nf * 8 + 2 * (lane & 3);
            Ts[r * 68 + cn]           = acc[ms][nf][0];
            Ts[r * 68 + cn + 1]       = acc[ms][nf][1];
            Ts[(r + 8) * 68 + cn]     = acc[ms][nf][2];
            Ts[(r + 8) * 68 + cn + 1] = acc[ms][nf][3];
        }
    }
    __syncthreads();

    {
        int row = tid >> 2;
        int gm = m0 + row;
        if (gm < LSZ) {
#pragma unroll
            for (int q = 0; q < 4; q++) {
                int cl = (tid & 3) * 16 + q * 4;
                int gn = n0 + cl;
                if (gn < LSZ)
                    *(float4*)(g_att + ((size_t)b * LSZ + gm) * LSZ + gn) =
                        *(const float4*)&Ts[row * 68 + cl];
            }
        }
    }
    {
        int rr = tid >> 2;
        int gr = n0 + rr;
        if (gr < LSZ) {
#pragma unroll
            for (int q = 0; q < 4; q++) {
                int l0 = (tid & 3) * 16 + q * 4;
                int gl = m0 + l0;
                if (gl < LSZ) {
                    float4 o;
                    o.x = Ts[(l0 + 0) * 68 + rr];
                    o.y = Ts[(l0 + 1) * 68 + rr];
                    o.z = Ts[(l0 + 2) * 68 + rr];
                    o.w = Ts[(l0 + 3) * 68 + rr];
                    *(float4*)(g_attT + ((size_t)b * LSZ + gr) * LSZ + gl) = o;
                }
            }
        }
    }
}

// ---------------- fused softmax / stats / top-3 / counterpart ----------------
__device__ __forceinline__ bool tk_better(float av, int ai, float bv, int bi) {
    return (av > bv) || (av == bv && ai < bi);
}
__device__ __forceinline__ void tk_insert(float nv, int ni,
                                          float& v0, int& i0, float& v1, int& i1, float& v2, int& i2) {
    if (tk_better(nv, ni, v0, i0)) { v2 = v1; i2 = i1; v1 = v0; i1 = i0; v0 = nv; i0 = ni; }
    else if (tk_better(nv, ni, v1, i1)) { v2 = v1; i2 = i1; v1 = nv; i1 = ni; }
    else if (tk_better(nv, ni, v2, i2)) { v2 = nv; i2 = ni; }
}

__global__ void attproc_kernel(const int* __restrict__ ll, const int* __restrict__ rl) {
    int side = blockIdx.y;
    const float* attRows   = side ? g_attT : g_att;
    const unsigned* selfH  = side ? g_rvh : g_lvh;
    const unsigned* selfL  = side ? g_rvl : g_lvl;
    const unsigned* othH   = side ? g_lvh : g_rvh;
    const unsigned* othL   = side ? g_lvl : g_rvl;
    const int* lenSelf     = side ? rl : ll;
    const int* lenOther    = side ? ll : rl;
    unsigned* outX         = side ? g_rcx : g_lcx;

    int wid  = blockIdx.x * (blockDim.x >> 5) + (threadIdx.x >> 5);
    int lane = threadIdx.x & 31;
    int b = wid / LSZ, i = wid % LSZ;
    if (b >= BSZ) return;
    if (i >= lenSelf[b]) return;
    int n = lenOther[b];
    const float* row = attRows + ((size_t)b * LSZ + i) * LSZ;
    const unsigned FULL = 0xffffffffu;

    float rv[5];
#pragma unroll
    for (int k = 0; k < 5; k++) {
        int j = lane + 32 * k;
        rv[k] = (j < n) ? row[j] : -3.0e38f;
    }

    // lane-local top-3
    float v0 = -3.0e38f, v1 = -3.0e38f, v2 = -3.0e38f;
    int i0 = 0x7fffffff, i1 = 0x7fffffff, i2 = 0x7fffffff;
#pragma unroll
    for (int k = 0; k < 5; k++) {
        int j = lane + 32 * k;
        if (j < n) tk_insert(rv[k], j, v0, i0, v1, i1, v2, i2);
    }

    // 3-round pop-argmax: butterfly max of heads, owner pops
    float tv[3]; int ti[3];
#pragma unroll
    for (int r = 0; r < 3; r++) {
        float cv = v0; int ci = i0;
#pragma unroll
        for (int off = 16; off >= 1; off >>= 1) {
            float ov = __shfl_xor_sync(FULL, cv, off);
            int   oi = __shfl_xor_sync(FULL, ci, off);
            if (tk_better(ov, oi, cv, ci)) { cv = ov; ci = oi; }
        }
        tv[r] = cv; ti[r] = ci;
        if (i0 == ci) { v0 = v1; i0 = i1; v1 = v2; i1 = i2; v2 = -3.0e38f; i2 = 0x7fffffff; }
    }
    float m = tv[0];

    float S = 0.f, S2 = 0.f;
#pragma unroll
    for (int k = 0; k < 5; k++) {
        int j = lane + 32 * k;
        if (j < n) {
            float e = __expf(rv[k] - m);
            S += e; S2 += e * e;
        }
    }
#pragma unroll
    for (int off = 16; off >= 1; off >>= 1) {
        S  += __shfl_xor_sync(FULL, S,  off);
        S2 += __shfl_xor_sync(FULL, S2, off);
    }

    float rlenf = (float)n;
    float mean  = 1.0f / rlenf;
    float s2    = S2 / (S * S);
    float w     = (s2 / rlenf - mean * mean) / fmaxf(mean, 0.001f);

    float a0 = 1.0f, a1 = __expf(tv[1] - tv[0]), a2 = __expf(tv[2] - tv[0]);
    float inv = __fdividef(1.0f, a0 + a1 + a2);
    a0 *= inv; a1 *= inv; a2 *= inv;

    size_t r0 = ((size_t)b * LSZ + ti[0]) * DPW;
    size_t r1 = ((size_t)b * LSZ + ti[1]) * DPW;
    size_t r2 = ((size_t)b * LSZ + ti[2]) * DPW;
    size_t rs = ((size_t)b * LSZ + i) * DPW;

#pragma unroll
    for (int k = 0; k < 6; k++) {
        int p = lane + 32 * k;
        if (p < DPW) {
            float x0 = 0.f, x1 = 0.f;
            if (p < 175) {
                float2 e0 = rec2(othH[r0 + p], othL[r0 + p]);
                float2 e1 = rec2(othH[r1 + p], othL[r1 + p]);
                float2 e2 = rec2(othH[r2 + p], othL[r2 + p]);
                float2 s  = rec2(selfH[rs + p], selfL[rs + p]);
                float c0 = a0 * e0.x + a1 * e1.x + a2 * e2.x;
                float c1 = a0 * e0.y + a1 * e1.y + a2 * e2.y;
                x0 = w * fabsf(s.x - c0);
                x1 = w * fabsf(s.y - c1);
            }
            __half2 hx = __floats2half2_rn(x0, x1);
            outX[rs + p] = *(unsigned*)&hx;
        }
    }
}

// =====================================================================
// conv GEMM fused with relu-max pooling. fp16 single-term: acc = X*W.
// 128(m, tiles m0 in {0,96}) x 128(n = 20 o-groups of 6 ch + 8 pad),
// cp.async 2-stage, ldmatrix. Epilogue: acc -> smem Z -> pooling -> atomicMax.
// stage layout (words): A[128*CWP] | B[128*CWP] = 5120 words (20480 B)
// =====================================================================
#define CSTG_W (2 * 128 * CWP)
#define COFF_A 0
#define COFF_B (128 * CWP)
#define CV_SMEM (128 * ZP2 * 4)   // 66048 >= 2*CSTG_W*4 = 40960

__global__ __launch_bounds__(256) void conv_gemm_kernel(const int* __restrict__ llen,
                                                        const int* __restrict__ rlen,
                                                        const float* __restrict__ cb1,
                                                        const float* __restrict__ cb2,
                                                        const float* __restrict__ cb3) {
    extern __shared__ unsigned smw[];
    int zb = blockIdx.z;
    int side = zb >> 9, b = zb & 511;
    int mt = blockIdx.x;               // 0: rows 0..127, 1: rows 96..159(+pad)
    int tileN = blockIdx.y;            // 0..4
    int len = side ? rlen[b] : llen[b];
    if (mt == 1 && len < 127) return;
    int m0 = mt * 96;
    int n0 = tileN * 128;

    const unsigned* Ax = (side ? g_rcx : g_lcx) + (size_t)b * LSZ * DPW;

    int tid  = threadIdx.x;
    int lane = tid & 31;
    int wid  = tid >> 5;
    int wm   = wid & 3;                // 4 m-groups of 32
    int wn   = wid >> 2;               // 2 n-groups of 64

    unsigned sbase = (unsigned)__cvta_generic_to_shared(smw);

    // A copy: 2 chunks/thread (128 rows x 4 chunks); B copy: 2 chunks/thread
    float acc[2][8][4];
#pragma unroll
    for (int ms = 0; ms < 2; ms++)
#pragma unroll
        for (int nf = 0; nf < 8; nf++)
#pragma unroll
            for (int q = 0; q < 4; q++) acc[ms][nf][q] = 0.f;

#define CCOPY(kb, s) do {                                                         \
    unsigned sb0 = sbase + (s) * (CSTG_W * 4);                                    \
    _Pragma("unroll")                                                             \
    for (int q = 0; q < 2; q++) {                                                 \
        int cid = tid + 256 * q;                                                  \
        int r = cid >> 2, c = cid & 3;                                            \
        bool aok = (m0 + r) < LSZ;                                                \
        cp16(sb0 + (COFF_A + r * CWP + c * 4) * 4,                                \
             Ax + (size_t)(aok ? m0 + r : 0) * DPW + (kb) * 16 + c * 4, aok);     \
        cp16(sb0 + (COFF_B + r * CWP + c * 4) * 4,                                \
             g_wallh + (size_t)(n0 + r) * DPW + (kb) * 16 + c * 4, true);         \
    }                                                                             \
} while (0)

    CCOPY(0, 0);
    cpcommit();

    for (int kb = 0; kb < NKB; kb++) {
        if (kb + 1 < NKB) {
            CCOPY(kb + 1, (kb + 1) & 1);
            cpcommit();
            cpwait<1>();
        } else {
            cpwait<0>();
        }
        __syncthreads();

        unsigned sb0 = sbase + (kb & 1) * (CSTG_W * 4);
#pragma unroll
        for (int ks = 0; ks < 2; ks++) {
            unsigned af[2][4];
#pragma unroll
            for (int ms = 0; ms < 2; ms++) {
                int r = wm * 32 + ms * 16 + (lane & 7) + ((lane >> 3) & 1) * 8;
                int c = ks * 2 + (lane >> 4);
                ldx4(af[ms], sb0 + (COFF_A + r * CWP + c * 4) * 4);
            }
#pragma unroll
            for (int nfp = 0; nfp < 4; nfp++) {
                int rB = wn * 64 + nfp * 16 + ((lane >> 4) & 1) * 8 + (lane & 7);
                int cB = ks * 2 + ((lane >> 3) & 1);
                unsigned bf[4];
                ldx4(bf, sb0 + (COFF_B + rB * CWP + cB * 4) * 4);
#pragma unroll
                for (int ms = 0; ms < 2; ms++) {
                    mma16h(acc[ms][2 * nfp],     af[ms], bf[0], bf[1]);
                    mma16h(acc[ms][2 * nfp + 1], af[ms], bf[2], bf[3]);
                }
            }
        }
        __syncthreads();
    }
#undef CCOPY

    // ---- epilogue: accumulators -> smem Z[128][ZP2] (alias over stages) ----
    float* Zs = (float*)smw;
#pragma unroll
    for (int ms = 0; ms < 2; ms++) {
        int r = wm * 32 + ms * 16 + (lane >> 2);
#pragma unroll
        for (int nf = 0; nf < 8; nf++) {
            int jc = wn * 64 + nf * 8 + 2 * (lane & 3);
            Zs[r * ZP2 + jc]           = acc[ms][nf][0];
            Zs[r * ZP2 + jc + 1]       = acc[ms][nf][1];
            Zs[(r + 8) * ZP2 + jc]     = acc[ms][nf][2];
            Zs[(r + 8) * ZP2 + jc + 1] = acc[ms][nf][3];
        }
    }
    __syncthreads();

    // ---- pooling: 60 items = 20 o-groups x 3 conv types ----
    if (tid < 60) {
        int o_l = tid / 3, cv = tid % 3;
        int o_g = tileN * 20 + o_l;
        if (o_g < 100) {
            int cb = o_l * 6;
            float bias = (cv == 0) ? cb1[o_g] : (cv == 1 ? cb2[o_g] : cb3[o_g]);
            int k = cv + 1;
            int lo = (mt == 0) ? 0 : 126;
            int hi = min(len - k, (mt == 0) ? 125 : 159);
            if (hi >= lo) {
                float mx = 0.f;
                if (cv == 0) {
                    for (int t = lo; t <= hi; t++) {
                        int tl = t - m0;
                        mx = fmaxf(mx, Zs[tl * ZP2 + cb] + bias);
                    }
                } else if (cv == 1) {
                    for (int t = lo; t <= hi; t++) {
                        int tl = t - m0;
                        mx = fmaxf(mx, Zs[tl * ZP2 + cb + 1] + Zs[(tl + 1) * ZP2 + cb + 2] + bias);
                    }
                } else {
                    for (int t = lo; t <= hi; t++) {
                        int tl = t - m0;
                        mx = fmaxf(mx, Zs[tl * ZP2 + cb + 3] + Zs[(tl + 1) * ZP2 + cb + 4]
                                     + Zs[(tl + 2) * ZP2 + cb + 5] + bias);
                    }
                }
                int fidx = b * NCH + side * 300 + cv * 100 + o_g;
                atomicMax((int*)&g_feats[fidx], __float_as_int(mx));
            }
        }
    }
}

// ---------------- dense head ----------------
__global__ void dense_kernel(const float* __restrict__ dw1, const float* __restrict__ db1,
                             const float* __restrict__ dw2, const float* __restrict__ db2,
                             float* __restrict__ out) {
    int b = blockIdx.x;
    __shared__ float f[NCH];
    __shared__ float h[64];
    int tid = threadIdx.x;
    for (int j = tid; j < NCH; j += blockDim.x) f[j] = g_feats[(size_t)b * NCH + j];
    __syncthreads();
    if (tid < 60) {
        float s = db1[tid];
        for (int j = 0; j < NCH; j++) s += f[j] * dw1[j * 60 + tid];
        h[tid] = fmaxf(s, 0.f);
    }
    __syncthreads();
    if (tid < 2) {
        float s = db2[tid];
        for (int j = 0; j < 60; j++) s += h[j] * dw2[j * 2 + tid];
        out[b * 2 + tid] = s;
    }
}

// ---------------- launch ----------------
extern "C" void kernel_launch(void* const* d_in, const int* in_sizes, int n_in,
                              void* d_out, int out_size) {
    const int*   lt   = (const int*)d_in[0];
    const int*   la   = (const int*)d_in[1];
    const int*   ll   = (const int*)d_in[2];
    const int*   rt   = (const int*)d_in[3];
    const int*   ra   = (const int*)d_in[4];
    const int*   rl   = (const int*)d_in[5];
    const float* wemb = (const float*)d_in[6];
    const float* aemb = (const float*)d_in[7];
    const float* cw1  = (const float*)d_in[8];
    const float* cb1  = (const float*)d_in[9];
    const float* cw2  = (const float*)d_in[10];
    const float* cb2  = (const float*)d_in[11];
    const float* cw3  = (const float*)d_in[12];
    const float* cb3  = (const float*)d_in[13];
    const float* dw1  = (const float*)d_in[14];
    const float* db1  = (const float*)d_in[15];
    const float* dw2  = (const float*)d_in[16];
    const float* db2  = (const float*)d_in[17];
    float* out = (float*)d_out;

    const int attSmem  = AST_W * 4 * 2;   // 40960 bytes
    cudaFuncSetAttribute(conv_gemm_kernel,
                         cudaFuncAttributeMaxDynamicSharedMemorySize, CV_SMEM);
    cudaFuncSetAttribute(att_gemm_kernel,
                         cudaFuncAttributeMaxDynamicSharedMemorySize, attSmem);

    init_kernel<<<(BSZ * NCH + 255) / 256, 256>>>(cw1, cw2, cw3);
    gather_kernel<<<dim3(LSZ / 2, BSZ, 2), 192>>>(lt, la, rt, ra, wemb, aemb, ll, rl);
    att_gemm_kernel<<<dim3(3, 3, BSZ), 256, attSmem>>>(ll, rl);
    attproc_kernel<<<dim3((BSZ * LSZ) / 4, 2), 128>>>(ll, rl);
    conv_gemm_kernel<<<dim3(2, 5, 2 * BSZ), 256, CV_SMEM>>>(ll, rl, cb1, cb2, cb3);
    dense_kernel<<<BSZ, 128>>>(dw1, db1, dw2, db2, out);
}

// round 15
// speedup vs baseline: 1.3422x; 1.0173x over previous
#include <cuda_runtime.h>
#include <cuda_bf16.h>
#include <cuda_fp16.h>
#include <math.h>
#include <stdint.h>

// ---------------- problem constants ----------------
#define BSZ   512
#define LSZ   160
#define DDIM  350
#define DP    352     // padded D
#define DPW   176     // DP/2 packed words
#define NCH   600
#define NPAD  640
#define CWP   20      // smem word pitch (16 + 4 pad)
#define ZP2   129     // conv Z smem pitch (128 rows)

// ---------------- device scratch ----------------
__device__ unsigned g_lvh [(size_t)BSZ * LSZ * DPW];   // l_vec split hi (bf16x2)
__device__ unsigned g_lvl [(size_t)BSZ * LSZ * DPW];   // l_vec split lo
__device__ unsigned g_rvh [(size_t)BSZ * LSZ * DPW];
__device__ unsigned g_rvl [(size_t)BSZ * LSZ * DPW];
__device__ float    g_att [(size_t)BSZ * LSZ * LSZ];
__device__ float    g_attT[(size_t)BSZ * LSZ * LSZ];
__device__ unsigned g_lcx [(size_t)BSZ * LSZ * DPW];   // l_c as half2
__device__ unsigned g_rcx [(size_t)BSZ * LSZ * DPW];   // r_c as half2
__device__ unsigned g_wallh[(size_t)NPAD * DPW];       // wall fp16 (half2)
__device__ float    g_feats[(size_t)BSZ * NCH];

// ---------------- split helpers ----------------
__device__ __forceinline__ void split2(float a, float b, unsigned& hi, unsigned& lo) {
    __nv_bfloat162 h = __floats2bfloat162_rn(a, b);
    float ra = a - __bfloat162float(h.x);
    float rb = b - __bfloat162float(h.y);
    __nv_bfloat162 l = __floats2bfloat162_rn(ra, rb);
    hi = *(unsigned*)&h;
    lo = *(unsigned*)&l;
}
__device__ __forceinline__ float2 rec2(unsigned h, unsigned l) {
    float2 r;
    r.x = __uint_as_float(h << 16) + __uint_as_float(l << 16);
    r.y = __uint_as_float(h & 0xFFFF0000u) + __uint_as_float(l & 0xFFFF0000u);
    return r;
}
__device__ __forceinline__ void mma16(float* c, const unsigned* a, unsigned b0, unsigned b1) {
    asm volatile(
        "mma.sync.aligned.m16n8k16.row.col.f32.bf16.bf16.f32 "
        "{%0,%1,%2,%3}, {%4,%5,%6,%7}, {%8,%9}, {%0,%1,%2,%3};"
        : "+f"(c[0]), "+f"(c[1]), "+f"(c[2]), "+f"(c[3])
        : "r"(a[0]), "r"(a[1]), "r"(a[2]), "r"(a[3]), "r"(b0), "r"(b1));
}
__device__ __forceinline__ void mma16h(float* c, const unsigned* a, unsigned b0, unsigned b1) {
    asm volatile(
        "mma.sync.aligned.m16n8k16.row.col.f32.f16.f16.f32 "
        "{%0,%1,%2,%3}, {%4,%5,%6,%7}, {%8,%9}, {%0,%1,%2,%3};"
        : "+f"(c[0]), "+f"(c[1]), "+f"(c[2]), "+f"(c[3])
        : "r"(a[0]), "r"(a[1]), "r"(a[2]), "r"(a[3]), "r"(b0), "r"(b1));
}
__device__ __forceinline__ void ldx4(unsigned* r, unsigned addr) {
    asm volatile("ldmatrix.sync.aligned.m8n8.x4.shared.b16 {%0,%1,%2,%3}, [%4];"
                 : "=r"(r[0]), "=r"(r[1]), "=r"(r[2]), "=r"(r[3]) : "r"(addr));
}
__device__ __forceinline__ void cp16(unsigned dst, const void* src, bool pred) {
    int sz = pred ? 16 : 0;
    asm volatile("cp.async.ca.shared.global [%0], [%1], 16, %2;"
                 :: "r"(dst), "l"(src), "r"(sz));
}
__device__ __forceinline__ void cpcommit() { asm volatile("cp.async.commit_group;"); }
template<int N> __device__ __forceinline__ void cpwait() {
    asm volatile("cp.async.wait_group %0;" :: "n"(N));
}

// ---------------- merged init: zero feats + build permuted fp16 wall ------------
__global__ void init_kernel(const float* __restrict__ w1,
                            const float* __restrict__ w2,
                            const float* __restrict__ w3) {
    int idx = blockIdx.x * blockDim.x + threadIdx.x;
    if (idx < BSZ * NCH) g_feats[idx] = 0.f;
    if (idx < NPAD * DPW) {
        int nn = idx / DPW, p = idx % DPW;
        int tile = nn >> 7, j = nn & 127;
        int o = tile * 20 + j / 6;
        int g = j % 6;
        bool valid = (j < 120) && (o < 100);
        float v[2];
#pragma unroll
        for (int c = 0; c < 2; c++) {
            int k = 2 * p + c;
            float x = 0.f;
            if (valid && k < DDIM) {
                if      (g == 0) x = w1[o * DDIM + k];
                else if (g <= 2) x = w2[o * (DDIM * 2) + k * 2 + (g - 1)];
                else             x = w3[o * (DDIM * 3) + k * 3 + (g - 3)];
            }
            v[c] = x;
        }
        __half2 h = __floats2half2_rn(v[0], v[1]);
        g_wallh[idx] = *(unsigned*)&h;
    }
}

// ---------------- embedding gather v3: 8 floats/thread, uint4 stores ------------
__global__ void gather_kernel(const int* __restrict__ lt, const int* __restrict__ la,
                              const int* __restrict__ rt, const int* __restrict__ ra,
                              const float* __restrict__ wemb, const float* __restrict__ aemb,
                              const int* __restrict__ ll, const int* __restrict__ rl) {
    int sub = threadIdx.x / 48;              // 0..3  (row within block)
    int q   = threadIdx.x % 48;
    int l = blockIdx.x * 4 + sub;
    int b = blockIdx.y, side = blockIdx.z;
    int len = side ? rl[b] : ll[b];
    if (l >= len) return;                    // rows >= len never read downstream
    const int* tok = side ? rt : lt;
    const int* atr = side ? ra : la;
    size_t rowo = ((size_t)(b * LSZ + l)) * DPW;
    unsigned* dstH = (side ? g_rvh : g_lvh) + rowo;
    unsigned* dstL = (side ? g_rvl : g_lvl) + rowo;
    int t = tok[l * BSZ + b];
    int a = atr[l * BSZ + b];
    const float* wr = wemb + (size_t)t * 300;
    const float* ar = aemb + (size_t)a * 50;
    if (q < 44) {
        int d0 = q * 8;
        float v[8];
        if (d0 + 7 < 50) {                       // q <= 5: pure attr
            float2 p0 = *(const float2*)(ar + d0);
            float2 p1 = *(const float2*)(ar + d0 + 2);
            float2 p2 = *(const float2*)(ar + d0 + 4);
            float2 p3 = *(const float2*)(ar + d0 + 6);
            v[0] = p0.x; v[1] = p0.y; v[2] = p1.x; v[3] = p1.y;
            v[4] = p2.x; v[5] = p2.y; v[6] = p3.x; v[7] = p3.y;
        } else if (d0 == 48) {                   // q == 6: 2 attr + 6 word
            float2 p0 = *(const float2*)(ar + 48);
            float2 p1 = *(const float2*)(wr);
            float2 p2 = *(const float2*)(wr + 2);
            float2 p3 = *(const float2*)(wr + 4);
            v[0] = p0.x; v[1] = p0.y; v[2] = p1.x; v[3] = p1.y;
            v[4] = p2.x; v[5] = p2.y; v[6] = p3.x; v[7] = p3.y;
        } else if (d0 + 7 < DDIM) {              // q in [7,42]: pure word
            const float* wp = wr + (d0 - 50);
            float2 p0 = *(const float2*)(wp);
            float2 p1 = *(const float2*)(wp + 2);
            float2 p2 = *(const float2*)(wp + 4);
            float2 p3 = *(const float2*)(wp + 6);
            v[0] = p0.x; v[1] = p0.y; v[2] = p1.x; v[3] = p1.y;
            v[4] = p2.x; v[5] = p2.y; v[6] = p3.x; v[7] = p3.y;
        } else {                                  // q == 43 (d0=344): 6 word + 2 zero
            float2 p0 = *(const float2*)(wr + 294);
            float2 p1 = *(const float2*)(wr + 296);
            float2 p2 = *(const float2*)(wr + 298);
            v[0] = p0.x; v[1] = p0.y; v[2] = p1.x; v[3] = p1.y;
            v[4] = p2.x; v[5] = p2.y; v[6] = 0.f; v[7] = 0.f;
        }
        uint4 oh, olv;
        unsigned hi, lo;
        split2(v[0], v[1], hi, lo); oh.x = hi; olv.x = lo;
        split2(v[2], v[3], hi, lo); oh.y = hi; olv.y = lo;
        split2(v[4], v[5], hi, lo); oh.z = hi; olv.z = lo;
        split2(v[6], v[7], hi, lo); oh.w = hi; olv.w = lo;
        *(uint4*)(dstH + q * 4) = oh;
        *(uint4*)(dstL + q * 4) = olv;
    }
}

// =====================================================================
// att GEMM (round-9/13 proven): 64x64 tile, 8 warps (2m x 4n, 32x16
// warp tiles), cp.async 2-stage + ldmatrix, bf16 3-term split.
// =====================================================================
#define AST_AH 0
#define AST_AL (64 * CWP)
#define AST_BH (2 * 64 * CWP)
#define AST_BL (3 * 64 * CWP)
#define AST_W  (4 * 64 * CWP)
#define NKB    11

__global__ __launch_bounds__(256) void att_gemm_kernel(const int* __restrict__ llen,
                                                       const int* __restrict__ rlen) {
    extern __shared__ unsigned asw[];
    int b  = blockIdx.z;
    int m0 = blockIdx.x * 64;
    int n0 = blockIdx.y * 64;
    if (m0 >= llen[b] || n0 >= rlen[b]) return;

    const unsigned* Avh = g_lvh + (size_t)b * LSZ * DPW;
    const unsigned* Avl = g_lvl + (size_t)b * LSZ * DPW;
    const unsigned* Bvh = g_rvh + (size_t)b * LSZ * DPW;
    const unsigned* Bvl = g_rvl + (size_t)b * LSZ * DPW;

    int tid  = threadIdx.x;
    int lane = tid & 31;
    int wid  = tid >> 5;
    int wm   = wid & 1;
    int wn   = wid >> 1;

    unsigned sbase = (unsigned)__cvta_generic_to_shared(asw);

    int ar = tid >> 2, ac = tid & 3;
    bool aok = (m0 + ar) < LSZ;
    bool bok = (n0 + ar) < LSZ;
    const unsigned* asH = Avh + (size_t)(aok ? m0 + ar : 0) * DPW + ac * 4;
    const unsigned* asL = Avl + (size_t)(aok ? m0 + ar : 0) * DPW + ac * 4;
    const unsigned* bsH = Bvh + (size_t)(bok ? n0 + ar : 0) * DPW + ac * 4;
    const unsigned* bsL = Bvl + (size_t)(bok ? n0 + ar : 0) * DPW + ac * 4;
    unsigned dA = (ar * CWP + ac * 4);

    float acc[2][2][4];
#pragma unroll
    for (int ms = 0; ms < 2; ms++)
#pragma unroll
        for (int nf = 0; nf < 2; nf++)
#pragma unroll
            for (int q = 0; q < 4; q++) acc[ms][nf][q] = 0.f;

#define ACOPY(kb, s) do {                                                \
    unsigned sb0 = sbase + (s) * (AST_W * 4);                            \
    cp16(sb0 + (AST_AH + dA) * 4, asH + (kb) * 16, aok);                 \
    cp16(sb0 + (AST_AL + dA) * 4, asL + (kb) * 16, aok);                 \
    cp16(sb0 + (AST_BH + dA) * 4, bsH + (kb) * 16, bok);                 \
    cp16(sb0 + (AST_BL + dA) * 4, bsL + (kb) * 16, bok);                 \
} while (0)

    ACOPY(0, 0);
    cpcommit();

    for (int kb = 0; kb < NKB; kb++) {
        if (kb + 1 < NKB) {
            ACOPY(kb + 1, (kb + 1) & 1);
            cpcommit();
            cpwait<1>();
        } else {
            cpwait<0>();
        }
        __syncthreads();

        unsigned sb0 = sbase + (kb & 1) * (AST_W * 4);
#pragma unroll
        for (int ks = 0; ks < 2; ks++) {
            unsigned ahf[2][4], alf[2][4];
#pragma unroll
            for (int ms = 0; ms < 2; ms++) {
                int r = wm * 32 + ms * 16 + (lane & 7) + ((lane >> 3) & 1) * 8;
                int c = ks * 2 + (lane >> 4);
                ldx4(ahf[ms], sb0 + (AST_AH + r * CWP + c * 4) * 4);
                ldx4(alf[ms], sb0 + (AST_AL + r * CWP + c * 4) * 4);
            }
            int rB = wn * 16 + ((lane >> 4) & 1) * 8 + (lane & 7);
            int cB = ks * 2 + ((lane >> 3) & 1);
            unsigned bh[4], bl[4];
            ldx4(bh, sb0 + (AST_BH + rB * CWP + cB * 4) * 4);
            ldx4(bl, sb0 + (AST_BL + rB * CWP + cB * 4) * 4);
#pragma unroll
            for (int ms = 0; ms < 2; ms++) {
                mma16(acc[ms][0], ahf[ms], bh[0], bh[1]);
                mma16(acc[ms][0], ahf[ms], bl[0], bl[1]);
                mma16(acc[ms][0], alf[ms], bh[0], bh[1]);
                mma16(acc[ms][1], ahf[ms], bh[2], bh[3]);
                mma16(acc[ms][1], ahf[ms], bl[2], bl[3]);
                mma16(acc[ms][1], alf[ms], bh[2], bh[3]);
            }
        }
        __syncthreads();
    }
#undef ACOPY

    float* Ts = (float*)asw;
#pragma unroll
    for (int ms = 0; ms < 2; ms++) {
        int r = wm * 32 + ms * 16 + (lane >> 2);
#pragma unroll
        for (int nf = 0; nf < 2; nf++) {
            int cn = wn * 16 + nf * 8 + 2 * (lane & 3);
            Ts[r * 68 + cn]           = acc[ms][nf][0];
            Ts[r * 68 + cn + 1]       = acc[ms][nf][1];
            Ts[(r + 8) * 68 + cn]     = acc[ms][nf][2];
            Ts[(r + 8) * 68 + cn + 1] = acc[ms][nf][3];
        }
    }
    __syncthreads();

    {
        int row = tid >> 2;
        int gm = m0 + row;
        if (gm < LSZ) {
#pragma unroll
            for (int q = 0; q < 4; q++) {
                int cl = (tid & 3) * 16 + q * 4;
                int gn = n0 + cl;
                if (gn < LSZ)
                    *(float4*)(g_att + ((size_t)b * LSZ + gm) * LSZ + gn) =
                        *(const float4*)&Ts[row * 68 + cl];
            }
        }
    }
    {
        int rr = tid >> 2;
        int gr = n0 + rr;
        if (gr < LSZ) {
#pragma unroll
            for (int q = 0; q < 4; q++) {
                int l0 = (tid & 3) * 16 + q * 4;
                int gl = m0 + l0;
                if (gl < LSZ) {
                    float4 o;
                    o.x = Ts[(l0 + 0) * 68 + rr];
                    o.y = Ts[(l0 + 1) * 68 + rr];
                    o.z = Ts[(l0 + 2) * 68 + rr];
                    o.w = Ts[(l0 + 3) * 68 + rr];
                    *(float4*)(g_attT + ((size_t)b * LSZ + gr) * LSZ + gl) = o;
                }
            }
        }
    }
}

// ---------------- fused softmax / stats / top-3 / counterpart ----------------
__device__ __forceinline__ bool tk_better(float av, int ai, float bv, int bi) {
    return (av > bv) || (av == bv && ai < bi);
}
__device__ __forceinline__ void tk_insert(float nv, int ni,
                                          float& v0, int& i0, float& v1, int& i1, float& v2, int& i2) {
    if (tk_better(nv, ni, v0, i0)) { v2 = v1; i2 = i1; v1 = v0; i1 = i0; v0 = nv; i0 = ni; }
    else if (tk_better(nv, ni, v1, i1)) { v2 = v1; i2 = i1; v1 = nv; i1 = ni; }
    else if (tk_better(nv, ni, v2, i2)) { v2 = nv; i2 = ni; }
}

__global__ void attproc_kernel(const int* __restrict__ ll, const int* __restrict__ rl) {
    int side = blockIdx.y;
    const float* attRows   = side ? g_attT : g_att;
    const unsigned* selfH  = side ? g_rvh : g_lvh;
    const unsigned* selfL  = side ? g_rvl : g_lvl;
    const unsigned* othH   = side ? g_lvh : g_rvh;
    const unsigned* othL   = side ? g_lvl : g_rvl;
    const int* lenSelf     = side ? rl : ll;
    const int* lenOther    = side ? ll : rl;
    unsigned* outX         = side ? g_rcx : g_lcx;

    int wid  = blockIdx.x * (blockDim.x >> 5) + (threadIdx.x >> 5);
    int lane = threadIdx.x & 31;
    int b = wid / LSZ, i = wid % LSZ;
    if (b >= BSZ) return;
    if (i >= lenSelf[b]) return;
    int n = lenOther[b];
    const float* row = attRows + ((size_t)b * LSZ + i) * LSZ;
    const unsigned FULL = 0xffffffffu;

    size_t rs = ((size_t)b * LSZ + i) * DPW;

    // prefetch self-vector row (independent of reductions)
    unsigned shw[6], slw[6];
#pragma unroll
    for (int k = 0; k < 6; k++) {
        int p = lane + 32 * k;
        shw[k] = (p < DPW) ? selfH[rs + p] : 0u;
        slw[k] = (p < DPW) ? selfL[rs + p] : 0u;
    }

    float rv[5];
#pragma unroll
    for (int k = 0; k < 5; k++) {
        int j = lane + 32 * k;
        rv[k] = (j < n) ? row[j] : -3.0e38f;
    }

    // lane-local top-3
    float v0 = -3.0e38f, v1 = -3.0e38f, v2 = -3.0e38f;
    int i0 = 0x7fffffff, i1 = 0x7fffffff, i2 = 0x7fffffff;
#pragma unroll
    for (int k = 0; k < 5; k++) {
        int j = lane + 32 * k;
        if (j < n) tk_insert(rv[k], j, v0, i0, v1, i1, v2, i2);
    }

    // 3-round pop-argmax
    float tv[3]; int ti[3];
#pragma unroll
    for (int r = 0; r < 3; r++) {
        float cv = v0; int ci = i0;
#pragma unroll
        for (int off = 16; off >= 1; off >>= 1) {
            float ov = __shfl_xor_sync(FULL, cv, off);
            int   oi = __shfl_xor_sync(FULL, ci, off);
            if (tk_better(ov, oi, cv, ci)) { cv = ov; ci = oi; }
        }
        tv[r] = cv; ti[r] = ci;
        if (i0 == ci) { v0 = v1; i0 = i1; v1 = v2; i1 = i2; v2 = -3.0e38f; i2 = 0x7fffffff; }
    }
    float m = tv[0];

    float S = 0.f, S2 = 0.f;
#pragma unroll
    for (int k = 0; k < 5; k++) {
        int j = lane + 32 * k;
        if (j < n) {
            float e = __expf(rv[k] - m);
            S += e; S2 += e * e;
        }
    }
#pragma unroll
    for (int off = 16; off >= 1; off >>= 1) {
        S  += __shfl_xor_sync(FULL, S,  off);
        S2 += __shfl_xor_sync(FULL, S2, off);
    }

    float rlenf = (float)n;
    float mean  = 1.0f / rlenf;
    float s2    = S2 / (S * S);
    float w     = (s2 / rlenf - mean * mean) / fmaxf(mean, 0.001f);

    float a0 = 1.0f, a1 = __expf(tv[1] - tv[0]), a2 = __expf(tv[2] - tv[0]);
    float inv = __fdividef(1.0f, a0 + a1 + a2);
    a0 *= inv; a1 *= inv; a2 *= inv;

    size_t r0 = ((size_t)b * LSZ + ti[0]) * DPW;
    size_t r1 = ((size_t)b * LSZ + ti[1]) * DPW;
    size_t r2 = ((size_t)b * LSZ + ti[2]) * DPW;

#pragma unroll
    for (int k = 0; k < 6; k++) {
        int p = lane + 32 * k;
        if (p < DPW) {
            float x0 = 0.f, x1 = 0.f;
            if (p < 175) {
                float2 e0 = rec2(othH[r0 + p], othL[r0 + p]);
                float2 e1 = rec2(othH[r1 + p], othL[r1 + p]);
                float2 e2 = rec2(othH[r2 + p], othL[r2 + p]);
                float2 s  = rec2(shw[k], slw[k]);
                float c0 = a0 * e0.x + a1 * e1.x + a2 * e2.x;
                float c1 = a0 * e0.y + a1 * e1.y + a2 * e2.y;
                x0 = w * fabsf(s.x - c0);
                x1 = w * fabsf(s.y - c1);
            }
            __half2 hx = __floats2half2_rn(x0, x1);
            outX[rs + p] = *(unsigned*)&hx;
        }
    }
}

// =====================================================================
// conv GEMM fused with relu-max pooling (round-13 proven, unchanged)
// =====================================================================
#define CSTG_W (2 * 128 * CWP)
#define COFF_A 0
#define COFF_B (128 * CWP)
#define CV_SMEM (128 * ZP2 * 4)   // 66048 >= 2*CSTG_W*4 = 40960

__global__ __launch_bounds__(256) void conv_gemm_kernel(const int* __restrict__ llen,
                                                        const int* __restrict__ rlen,
                                                        const float* __restrict__ cb1,
                                                        const float* __restrict__ cb2,
                                                        const float* __restrict__ cb3) {
    extern __shared__ unsigned smw[];
    int zb = blockIdx.z;
    int side = zb >> 9, b = zb & 511;
    int mt = blockIdx.x;               // 0: rows 0..127, 1: rows 96..159(+pad)
    int tileN = blockIdx.y;            // 0..4
    int len = side ? rlen[b] : llen[b];
    if (mt == 1 && len < 127) return;
    int m0 = mt * 96;
    int n0 = tileN * 128;

    const unsigned* Ax = (side ? g_rcx : g_lcx) + (size_t)b * LSZ * DPW;

    int tid  = threadIdx.x;
    int lane = tid & 31;
    int wid  = tid >> 5;
    int wm   = wid & 3;
    int wn   = wid >> 2;

    unsigned sbase = (unsigned)__cvta_generic_to_shared(smw);

    float acc[2][8][4];
#pragma unroll
    for (int ms = 0; ms < 2; ms++)
#pragma unroll
        for (int nf = 0; nf < 8; nf++)
#pragma unroll
            for (int q = 0; q < 4; q++) acc[ms][nf][q] = 0.f;

#define CCOPY(kb, s) do {                                                         \
    unsigned sb0 = sbase + (s) * (CSTG_W * 4);                                    \
    _Pragma("unroll")                                                             \
    for (int q = 0; q < 2; q++) {                                                 \
        int cid = tid + 256 * q;                                                  \
        int r = cid >> 2, c = cid & 3;                                            \
        bool aok = (m0 + r) < LSZ;                                                \
        cp16(sb0 + (COFF_A + r * CWP + c * 4) * 4,                                \
             Ax + (size_t)(aok ? m0 + r : 0) * DPW + (kb) * 16 + c * 4, aok);     \
        cp16(sb0 + (COFF_B + r * CWP + c * 4) * 4,                                \
             g_wallh + (size_t)(n0 + r) * DPW + (kb) * 16 + c * 4, true);         \
    }                                                                             \
} while (0)

    CCOPY(0, 0);
    cpcommit();

    for (int kb = 0; kb < NKB; kb++) {
        if (kb + 1 < NKB) {
            CCOPY(kb + 1, (kb + 1) & 1);
            cpcommit();
            cpwait<1>();
        } else {
            cpwait<0>();
        }
        __syncthreads();

        unsigned sb0 = sbase + (kb & 1) * (CSTG_W * 4);
#pragma unroll
        for (int ks = 0; ks < 2; ks++) {
            unsigned af[2][4];
#pragma unroll
            for (int ms = 0; ms < 2; ms++) {
                int r = wm * 32 + ms * 16 + (lane & 7) + ((lane >> 3) & 1) * 8;
                int c = ks * 2 + (lane >> 4);
                ldx4(af[ms], sb0 + (COFF_A + r * CWP + c * 4) * 4);
            }
#pragma unroll
            for (int nfp = 0; nfp < 4; nfp++) {
                int rB = wn * 64 + nfp * 16 + ((lane >> 4) & 1) * 8 + (lane & 7);
                int cB = ks * 2 + ((lane >> 3) & 1);
                unsigned bf[4];
                ldx4(bf, sb0 + (COFF_B + rB * CWP + cB * 4) * 4);
#pragma unroll
                for (int ms = 0; ms < 2; ms++) {
                    mma16h(acc[ms][2 * nfp],     af[ms], bf[0], bf[1]);
                    mma16h(acc[ms][2 * nfp + 1], af[ms], bf[2], bf[3]);
                }
            }
        }
        __syncthreads();
    }
#undef CCOPY

    float* Zs = (float*)smw;
#pragma unroll
    for (int ms = 0; ms < 2; ms++) {
        int r = wm * 32 + ms * 16 + (lane >> 2);
#pragma unroll
        for (int nf = 0; nf < 8; nf++) {
            int jc = wn * 64 + nf * 8 + 2 * (lane & 3);
            Zs[r * ZP2 + jc]           = acc[ms][nf][0];
            Zs[r * ZP2 + jc + 1]       = acc[ms][nf][1];
            Zs[(r + 8) * ZP2 + jc]     = acc[ms][nf][2];
            Zs[(r + 8) * ZP2 + jc + 1] = acc[ms][nf][3];
        }
    }
    __syncthreads();

    if (tid < 60) {
        int o_l = tid / 3, cv = tid % 3;
        int o_g = tileN * 20 + o_l;
        if (o_g < 100) {
            int cb = o_l * 6;
            float bias = (cv == 0) ? cb1[o_g] : (cv == 1 ? cb2[o_g] : cb3[o_g]);
            int k = cv + 1;
            int lo = (mt == 0) ? 0 : 126;
            int hi = min(len - k, (mt == 0) ? 125 : 159);
            if (hi >= lo) {
                float mx = 0.f;
                if (cv == 0) {
                    for (int t = lo; t <= hi; t++) {
                        int tl = t - m0;
                        mx = fmaxf(mx, Zs[tl * ZP2 + cb] + bias);
                    }
                } else if (cv == 1) {
                    for (int t = lo; t <= hi; t++) {
                        int tl = t - m0;
                        mx = fmaxf(mx, Zs[tl * ZP2 + cb + 1] + Zs[(tl + 1) * ZP2 + cb + 2] + bias);
                    }
                } else {
                    for (int t = lo; t <= hi; t++) {
                        int tl = t - m0;
                        mx = fmaxf(mx, Zs[tl * ZP2 + cb + 3] + Zs[(tl + 1) * ZP2 + cb + 4]
                                     + Zs[(tl + 2) * ZP2 + cb + 5] + bias);
                    }
                }
                int fidx = b * NCH + side * 300 + cv * 100 + o_g;
                atomicMax((int*)&g_feats[fidx], __float_as_int(mx));
            }
        }
    }
}

// ---------------- dense head ----------------
__global__ void dense_kernel(const float* __restrict__ dw1, const float* __restrict__ db1,
                             const float* __restrict__ dw2, const float* __restrict__ db2,
                             float* __restrict__ out) {
    int b = blockIdx.x;
    __shared__ float f[NCH];
    __shared__ float h[64];
    int tid = threadIdx.x;
    for (int j = tid; j < NCH; j += blockDim.x) f[j] = g_feats[(size_t)b * NCH + j];
    __syncthreads();
    if (tid < 60) {
        float s = db1[tid];
        for (int j = 0; j < NCH; j++) s += f[j] * dw1[j * 60 + tid];
        h[tid] = fmaxf(s, 0.f);
    }
    __syncthreads();
    if (tid < 2) {
        float s = db2[tid];
        for (int j = 0; j < 60; j++) s += h[j] * dw2[j * 2 + tid];
        out[b * 2 + tid] = s;
    }
}

// ---------------- launch ----------------
extern "C" void kernel_launch(void* const* d_in, const int* in_sizes, int n_in,
                              void* d_out, int out_size) {
    const int*   lt   = (const int*)d_in[0];
    const int*   la   = (const int*)d_in[1];
    const int*   ll   = (const int*)d_in[2];
    const int*   rt   = (const int*)d_in[3];
    const int*   ra   = (const int*)d_in[4];
    const int*   rl   = (const int*)d_in[5];
    const float* wemb = (const float*)d_in[6];
    const float* aemb = (const float*)d_in[7];
    const float* cw1  = (const float*)d_in[8];
    const float* cb1  = (const float*)d_in[9];
    const float* cw2  = (const float*)d_in[10];
    const float* cb2  = (const float*)d_in[11];
    const float* cw3  = (const float*)d_in[12];
    const float* cb3  = (const float*)d_in[13];
    const float* dw1  = (const float*)d_in[14];
    const float* db1  = (const float*)d_in[15];
    const float* dw2  = (const float*)d_in[16];
    const float* db2  = (const float*)d_in[17];
    float* out = (float*)d_out;

    const int attSmem = AST_W * 4 * 2;   // 40960 bytes
    cudaFuncSetAttribute(conv_gemm_kernel,
                         cudaFuncAttributeMaxDynamicSharedMemorySize, CV_SMEM);
    cudaFuncSetAttribute(att_gemm_kernel,
                         cudaFuncAttributeMaxDynamicSharedMemorySize, attSmem);

    init_kernel<<<(BSZ * NCH + 255) / 256, 256>>>(cw1, cw2, cw3);
    gather_kernel<<<dim3(LSZ / 4, BSZ, 2), 192>>>(lt, la, rt, ra, wemb, aemb, ll, rl);
    att_gemm_kernel<<<dim3(3, 3, BSZ), 256, attSmem>>>(ll, rl);
    attproc_kernel<<<dim3((BSZ * LSZ) / 4, 2), 128>>>(ll, rl);
    conv_gemm_kernel<<<dim3(2, 5, 2 * BSZ), 256, CV_SMEM>>>(ll, rl, cb1, cb2, cb3);
    dense_kernel<<<BSZ, 128>>>(dw1, db1, dw2, db2, out);
}

// round 16
// speedup vs baseline: 1.3891x; 1.0349x over previous
#include <cuda_runtime.h>
#include <cuda_bf16.h>
#include <cuda_fp16.h>
#include <math.h>
#include <stdint.h>

// ---------------- problem constants ----------------
#define BSZ   512
#define LSZ   160
#define DDIM  350
#define DP    352     // padded D
#define DPW   176     // DP/2 packed words
#define NCH   600
#define NPAD  640
#define CWP   20      // smem word pitch (16 + 4 pad)
#define ZP2   129     // conv Z smem pitch (128 rows)

// ---------------- device scratch ----------------
__device__ unsigned g_lvh [(size_t)BSZ * LSZ * DPW];   // l_vec split hi (bf16x2)
__device__ unsigned g_lvl [(size_t)BSZ * LSZ * DPW];   // l_vec split lo
__device__ unsigned g_rvh [(size_t)BSZ * LSZ * DPW];
__device__ unsigned g_rvl [(size_t)BSZ * LSZ * DPW];
__device__ float    g_att [(size_t)BSZ * LSZ * LSZ];
__device__ float    g_attT[(size_t)BSZ * LSZ * LSZ];
__device__ unsigned g_lcx [(size_t)BSZ * LSZ * DPW];   // l_c as half2
__device__ unsigned g_rcx [(size_t)BSZ * LSZ * DPW];   // r_c as half2
__device__ unsigned g_wallh[(size_t)NPAD * DPW];       // wall fp16 (half2)
__device__ float    g_feats[(size_t)BSZ * NCH];

// ---------------- split helpers ----------------
__device__ __forceinline__ void split2(float a, float b, unsigned& hi, unsigned& lo) {
    __nv_bfloat162 h = __floats2bfloat162_rn(a, b);
    float ra = a - __bfloat162float(h.x);
    float rb = b - __bfloat162float(h.y);
    __nv_bfloat162 l = __floats2bfloat162_rn(ra, rb);
    hi = *(unsigned*)&h;
    lo = *(unsigned*)&l;
}
__device__ __forceinline__ float2 rec2(unsigned h, unsigned l) {
    float2 r;
    r.x = __uint_as_float(h << 16) + __uint_as_float(l << 16);
    r.y = __uint_as_float(h & 0xFFFF0000u) + __uint_as_float(l & 0xFFFF0000u);
    return r;
}
__device__ __forceinline__ void mma16(float* c, const unsigned* a, unsigned b0, unsigned b1) {
    asm volatile(
        "mma.sync.aligned.m16n8k16.row.col.f32.bf16.bf16.f32 "
        "{%0,%1,%2,%3}, {%4,%5,%6,%7}, {%8,%9}, {%0,%1,%2,%3};"
        : "+f"(c[0]), "+f"(c[1]), "+f"(c[2]), "+f"(c[3])
        : "r"(a[0]), "r"(a[1]), "r"(a[2]), "r"(a[3]), "r"(b0), "r"(b1));
}
__device__ __forceinline__ void mma16h(float* c, const unsigned* a, unsigned b0, unsigned b1) {
    asm volatile(
        "mma.sync.aligned.m16n8k16.row.col.f32.f16.f16.f32 "
        "{%0,%1,%2,%3}, {%4,%5,%6,%7}, {%8,%9}, {%0,%1,%2,%3};"
        : "+f"(c[0]), "+f"(c[1]), "+f"(c[2]), "+f"(c[3])
        : "r"(a[0]), "r"(a[1]), "r"(a[2]), "r"(a[3]), "r"(b0), "r"(b1));
}
__device__ __forceinline__ void ldx4(unsigned* r, unsigned addr) {
    asm volatile("ldmatrix.sync.aligned.m8n8.x4.shared.b16 {%0,%1,%2,%3}, [%4];"
                 : "=r"(r[0]), "=r"(r[1]), "=r"(r[2]), "=r"(r[3]) : "r"(addr));
}
__device__ __forceinline__ void cp16(unsigned dst, const void* src, bool pred) {
    int sz = pred ? 16 : 0;
    asm volatile("cp.async.ca.shared.global [%0], [%1], 16, %2;"
                 :: "r"(dst), "l"(src), "r"(sz));
}
__device__ __forceinline__ void cpcommit() { asm volatile("cp.async.commit_group;"); }
template<int N> __device__ __forceinline__ void cpwait() {
    asm volatile("cp.async.wait_group %0;" :: "n"(N));
}

// ---------------- merged init: zero feats + build permuted fp16 wall ------------
__global__ void init_kernel(const float* __restrict__ w1,
                            const float* __restrict__ w2,
                            const float* __restrict__ w3) {
    int idx = blockIdx.x * blockDim.x + threadIdx.x;
    if (idx < BSZ * NCH) g_feats[idx] = 0.f;
    if (idx < NPAD * DPW) {
        int nn = idx / DPW, p = idx % DPW;
        int tile = nn >> 7, j = nn & 127;
        int o = tile * 20 + j / 6;
        int g = j % 6;
        bool valid = (j < 120) && (o < 100);
        float v[2];
#pragma unroll
        for (int c = 0; c < 2; c++) {
            int k = 2 * p + c;
            float x = 0.f;
            if (valid && k < DDIM) {
                if      (g == 0) x = w1[o * DDIM + k];
                else if (g <= 2) x = w2[o * (DDIM * 2) + k * 2 + (g - 1)];
                else             x = w3[o * (DDIM * 3) + k * 3 + (g - 3)];
            }
            v[c] = x;
        }
        __half2 h = __floats2half2_rn(v[0], v[1]);
        g_wallh[idx] = *(unsigned*)&h;
    }
}

// ---------------- embedding gather v3 (round-15 proven) ----------------
__global__ void gather_kernel(const int* __restrict__ lt, const int* __restrict__ la,
                              const int* __restrict__ rt, const int* __restrict__ ra,
                              const float* __restrict__ wemb, const float* __restrict__ aemb,
                              const int* __restrict__ ll, const int* __restrict__ rl) {
    int sub = threadIdx.x / 48;
    int q   = threadIdx.x % 48;
    int l = blockIdx.x * 4 + sub;
    int b = blockIdx.y, side = blockIdx.z;
    int len = side ? rl[b] : ll[b];
    if (l >= len) return;
    const int* tok = side ? rt : lt;
    const int* atr = side ? ra : la;
    size_t rowo = ((size_t)(b * LSZ + l)) * DPW;
    unsigned* dstH = (side ? g_rvh : g_lvh) + rowo;
    unsigned* dstL = (side ? g_rvl : g_lvl) + rowo;
    int t = tok[l * BSZ + b];
    int a = atr[l * BSZ + b];
    const float* wr = wemb + (size_t)t * 300;
    const float* ar = aemb + (size_t)a * 50;
    if (q < 44) {
        int d0 = q * 8;
        float v[8];
        if (d0 + 7 < 50) {
            float2 p0 = *(const float2*)(ar + d0);
            float2 p1 = *(const float2*)(ar + d0 + 2);
            float2 p2 = *(const float2*)(ar + d0 + 4);
            float2 p3 = *(const float2*)(ar + d0 + 6);
            v[0] = p0.x; v[1] = p0.y; v[2] = p1.x; v[3] = p1.y;
            v[4] = p2.x; v[5] = p2.y; v[6] = p3.x; v[7] = p3.y;
        } else if (d0 == 48) {
            float2 p0 = *(const float2*)(ar + 48);
            float2 p1 = *(const float2*)(wr);
            float2 p2 = *(const float2*)(wr + 2);
            float2 p3 = *(const float2*)(wr + 4);
            v[0] = p0.x; v[1] = p0.y; v[2] = p1.x; v[3] = p1.y;
            v[4] = p2.x; v[5] = p2.y; v[6] = p3.x; v[7] = p3.y;
        } else if (d0 + 7 < DDIM) {
            const float* wp = wr + (d0 - 50);
            float2 p0 = *(const float2*)(wp);
            float2 p1 = *(const float2*)(wp + 2);
            float2 p2 = *(const float2*)(wp + 4);
            float2 p3 = *(const float2*)(wp + 6);
            v[0] = p0.x; v[1] = p0.y; v[2] = p1.x; v[3] = p1.y;
            v[4] = p2.x; v[5] = p2.y; v[6] = p3.x; v[7] = p3.y;
        } else {
            float2 p0 = *(const float2*)(wr + 294);
            float2 p1 = *(const float2*)(wr + 296);
            float2 p2 = *(const float2*)(wr + 298);
            v[0] = p0.x; v[1] = p0.y; v[2] = p1.x; v[3] = p1.y;
            v[4] = p2.x; v[5] = p2.y; v[6] = 0.f; v[7] = 0.f;
        }
        uint4 oh, olv;
        unsigned hi, lo;
        split2(v[0], v[1], hi, lo); oh.x = hi; olv.x = lo;
        split2(v[2], v[3], hi, lo); oh.y = hi; olv.y = lo;
        split2(v[4], v[5], hi, lo); oh.z = hi; olv.z = lo;
        split2(v[6], v[7], hi, lo); oh.w = hi; olv.w = lo;
        *(uint4*)(dstH + q * 4) = oh;
        *(uint4*)(dstL + q * 4) = olv;
    }
}

// =====================================================================
// att GEMM: 64x64 tile, 8 warps (2m x 4n, 32x16 warp tiles), cp.async
// 2-stage single-sync pipeline + ldmatrix, bf16 3-term split.
// =====================================================================
#define AST_AH 0
#define AST_AL (64 * CWP)
#define AST_BH (2 * 64 * CWP)
#define AST_BL (3 * 64 * CWP)
#define AST_W  (4 * 64 * CWP)
#define NKB    11

__global__ __launch_bounds__(256) void att_gemm_kernel(const int* __restrict__ llen,
                                                       const int* __restrict__ rlen) {
    extern __shared__ unsigned asw[];
    int b  = blockIdx.z;
    int m0 = blockIdx.x * 64;
    int n0 = blockIdx.y * 64;
    int lm = llen[b], rn = rlen[b];
    if (m0 >= lm || n0 >= rn) return;

    const unsigned* Avh = g_lvh + (size_t)b * LSZ * DPW;
    const unsigned* Avl = g_lvl + (size_t)b * LSZ * DPW;
    const unsigned* Bvh = g_rvh + (size_t)b * LSZ * DPW;
    const unsigned* Bvl = g_rvl + (size_t)b * LSZ * DPW;

    int tid  = threadIdx.x;
    int lane = tid & 31;
    int wid  = tid >> 5;
    int wm   = wid & 1;
    int wn   = wid >> 1;

    unsigned sbase = (unsigned)__cvta_generic_to_shared(asw);

    int ar = tid >> 2, ac = tid & 3;
    bool aok = (m0 + ar) < LSZ;
    bool bok = (n0 + ar) < LSZ;
    const unsigned* asH = Avh + (size_t)(aok ? m0 + ar : 0) * DPW + ac * 4;
    const unsigned* asL = Avl + (size_t)(aok ? m0 + ar : 0) * DPW + ac * 4;
    const unsigned* bsH = Bvh + (size_t)(bok ? n0 + ar : 0) * DPW + ac * 4;
    const unsigned* bsL = Bvl + (size_t)(bok ? n0 + ar : 0) * DPW + ac * 4;
    unsigned dA = (ar * CWP + ac * 4);

    float acc[2][2][4];
#pragma unroll
    for (int ms = 0; ms < 2; ms++)
#pragma unroll
        for (int nf = 0; nf < 2; nf++)
#pragma unroll
            for (int q = 0; q < 4; q++) acc[ms][nf][q] = 0.f;

#define ACOPY(kb, s) do {                                                \
    unsigned sb0 = sbase + (s) * (AST_W * 4);                            \
    cp16(sb0 + (AST_AH + dA) * 4, asH + (kb) * 16, aok);                 \
    cp16(sb0 + (AST_AL + dA) * 4, asL + (kb) * 16, aok);                 \
    cp16(sb0 + (AST_BH + dA) * 4, bsH + (kb) * 16, bok);                 \
    cp16(sb0 + (AST_BL + dA) * 4, bsL + (kb) * 16, bok);                 \
} while (0)

    ACOPY(0, 0);
    cpcommit();

    for (int kb = 0; kb < NKB; kb++) {
        cpwait<0>();
        __syncthreads();
        if (kb + 1 < NKB) {
            ACOPY(kb + 1, (kb + 1) & 1);
            cpcommit();
        }

        unsigned sb0 = sbase + (kb & 1) * (AST_W * 4);
#pragma unroll
        for (int ks = 0; ks < 2; ks++) {
            unsigned ahf[2][4], alf[2][4];
#pragma unroll
            for (int ms = 0; ms < 2; ms++) {
                int r = wm * 32 + ms * 16 + (lane & 7) + ((lane >> 3) & 1) * 8;
                int c = ks * 2 + (lane >> 4);
                ldx4(ahf[ms], sb0 + (AST_AH + r * CWP + c * 4) * 4);
                ldx4(alf[ms], sb0 + (AST_AL + r * CWP + c * 4) * 4);
            }
            int rB = wn * 16 + ((lane >> 4) & 1) * 8 + (lane & 7);
            int cB = ks * 2 + ((lane >> 3) & 1);
            unsigned bh[4], bl[4];
            ldx4(bh, sb0 + (AST_BH + rB * CWP + cB * 4) * 4);
            ldx4(bl, sb0 + (AST_BL + rB * CWP + cB * 4) * 4);
#pragma unroll
            for (int ms = 0; ms < 2; ms++) {
                mma16(acc[ms][0], ahf[ms], bh[0], bh[1]);
                mma16(acc[ms][0], ahf[ms], bl[0], bl[1]);
                mma16(acc[ms][0], alf[ms], bh[0], bh[1]);
                mma16(acc[ms][1], ahf[ms], bh[2], bh[3]);
                mma16(acc[ms][1], ahf[ms], bl[2], bl[3]);
                mma16(acc[ms][1], alf[ms], bh[2], bh[3]);
            }
        }
    }
#undef ACOPY

    __syncthreads();   // all math done before Ts (no alias, but cheap safety for reuse below)
    float* Ts = (float*)asw;
#pragma unroll
    for (int ms = 0; ms < 2; ms++) {
        int r = wm * 32 + ms * 16 + (lane >> 2);
#pragma unroll
        for (int nf = 0; nf < 2; nf++) {
            int cn = wn * 16 + nf * 8 + 2 * (lane & 3);
            Ts[r * 68 + cn]           = acc[ms][nf][0];
            Ts[r * 68 + cn + 1]       = acc[ms][nf][1];
            Ts[(r + 8) * 68 + cn]     = acc[ms][nf][2];
            Ts[(r + 8) * 68 + cn + 1] = acc[ms][nf][3];
        }
    }
    __syncthreads();

    {   // att[b][l][r], only rows < lm, cols < rn are ever read
        int row = tid >> 2;
        int gm = m0 + row;
        if (gm < lm) {
#pragma unroll
            for (int q = 0; q < 4; q++) {
                int cl = (tid & 3) * 16 + q * 4;
                int gn = n0 + cl;
                if (gn < rn)
                    *(float4*)(g_att + ((size_t)b * LSZ + gm) * LSZ + gn) =
                        *(const float4*)&Ts[row * 68 + cl];
            }
        }
    }
    {   // attT[b][r][l]
        int rr = tid >> 2;
        int gr = n0 + rr;
        if (gr < rn) {
#pragma unroll
            for (int q = 0; q < 4; q++) {
                int l0 = (tid & 3) * 16 + q * 4;
                int gl = m0 + l0;
                if (gl < lm) {
                    float4 o;
                    o.x = Ts[(l0 + 0) * 68 + rr];
                    o.y = Ts[(l0 + 1) * 68 + rr];
                    o.z = Ts[(l0 + 2) * 68 + rr];
                    o.w = Ts[(l0 + 3) * 68 + rr];
                    *(float4*)(g_attT + ((size_t)b * LSZ + gr) * LSZ + gl) = o;
                }
            }
        }
    }
}

// ---------------- fused softmax / stats / top-3 / counterpart (round-13) --------
__device__ __forceinline__ bool tk_better(float av, int ai, float bv, int bi) {
    return (av > bv) || (av == bv && ai < bi);
}
__device__ __forceinline__ void tk_insert(float nv, int ni,
                                          float& v0, int& i0, float& v1, int& i1, float& v2, int& i2) {
    if (tk_better(nv, ni, v0, i0)) { v2 = v1; i2 = i1; v1 = v0; i1 = i0; v0 = nv; i0 = ni; }
    else if (tk_better(nv, ni, v1, i1)) { v2 = v1; i2 = i1; v1 = nv; i1 = ni; }
    else if (tk_better(nv, ni, v2, i2)) { v2 = nv; i2 = ni; }
}

__global__ void attproc_kernel(const int* __restrict__ ll, const int* __restrict__ rl) {
    int side = blockIdx.y;
    const float* attRows   = side ? g_attT : g_att;
    const unsigned* selfH  = side ? g_rvh : g_lvh;
    const unsigned* selfL  = side ? g_rvl : g_lvl;
    const unsigned* othH   = side ? g_lvh : g_rvh;
    const unsigned* othL   = side ? g_lvl : g_rvl;
    const int* lenSelf     = side ? rl : ll;
    const int* lenOther    = side ? ll : rl;
    unsigned* outX         = side ? g_rcx : g_lcx;

    int wid  = blockIdx.x * (blockDim.x >> 5) + (threadIdx.x >> 5);
    int lane = threadIdx.x & 31;
    int b = wid / LSZ, i = wid % LSZ;
    if (b >= BSZ) return;
    if (i >= lenSelf[b]) return;
    int n = lenOther[b];
    const float* row = attRows + ((size_t)b * LSZ + i) * LSZ;
    const unsigned FULL = 0xffffffffu;

    float rv[5];
#pragma unroll
    for (int k = 0; k < 5; k++) {
        int j = lane + 32 * k;
        rv[k] = (j < n) ? row[j] : -3.0e38f;
    }

    float v0 = -3.0e38f, v1 = -3.0e38f, v2 = -3.0e38f;
    int i0 = 0x7fffffff, i1 = 0x7fffffff, i2 = 0x7fffffff;
#pragma unroll
    for (int k = 0; k < 5; k++) {
        int j = lane + 32 * k;
        if (j < n) tk_insert(rv[k], j, v0, i0, v1, i1, v2, i2);
    }

    float tv[3]; int ti[3];
#pragma unroll
    for (int r = 0; r < 3; r++) {
        float cv = v0; int ci = i0;
#pragma unroll
        for (int off = 16; off >= 1; off >>= 1) {
            float ov = __shfl_xor_sync(FULL, cv, off);
            int   oi = __shfl_xor_sync(FULL, ci, off);
            if (tk_better(ov, oi, cv, ci)) { cv = ov; ci = oi; }
        }
        tv[r] = cv; ti[r] = ci;
        if (i0 == ci) { v0 = v1; i0 = i1; v1 = v2; i1 = i2; v2 = -3.0e38f; i2 = 0x7fffffff; }
    }
    float m = tv[0];

    float S = 0.f, S2 = 0.f;
#pragma unroll
    for (int k = 0; k < 5; k++) {
        int j = lane + 32 * k;
        if (j < n) {
            float e = __expf(rv[k] - m);
            S += e; S2 += e * e;
        }
    }
#pragma unroll
    for (int off = 16; off >= 1; off >>= 1) {
        S  += __shfl_xor_sync(FULL, S,  off);
        S2 += __shfl_xor_sync(FULL, S2, off);
    }

    float rlenf = (float)n;
    float mean  = 1.0f / rlenf;
    float s2    = S2 / (S * S);
    float w     = (s2 / rlenf - mean * mean) / fmaxf(mean, 0.001f);

    float a0 = 1.0f, a1 = __expf(tv[1] - tv[0]), a2 = __expf(tv[2] - tv[0]);
    float inv = __fdividef(1.0f, a0 + a1 + a2);
    a0 *= inv; a1 *= inv; a2 *= inv;

    size_t r0 = ((size_t)b * LSZ + ti[0]) * DPW;
    size_t r1 = ((size_t)b * LSZ + ti[1]) * DPW;
    size_t r2 = ((size_t)b * LSZ + ti[2]) * DPW;
    size_t rs = ((size_t)b * LSZ + i) * DPW;

#pragma unroll
    for (int k = 0; k < 6; k++) {
        int p = lane + 32 * k;
        if (p < DPW) {
            float x0 = 0.f, x1 = 0.f;
            if (p < 175) {
                float2 e0 = rec2(othH[r0 + p], othL[r0 + p]);
                float2 e1 = rec2(othH[r1 + p], othL[r1 + p]);
                float2 e2 = rec2(othH[r2 + p], othL[r2 + p]);
                float2 s  = rec2(selfH[rs + p], selfL[rs + p]);
                float c0 = a0 * e0.x + a1 * e1.x + a2 * e2.x;
                float c1 = a0 * e0.y + a1 * e1.y + a2 * e2.y;
                x0 = w * fabsf(s.x - c0);
                x1 = w * fabsf(s.y - c1);
            }
            __half2 hx = __floats2half2_rn(x0, x1);
            outX[rs + p] = *(unsigned*)&hx;
        }
    }
}

// =====================================================================
// conv GEMM fused with relu-max pooling, single-sync pipeline
// =====================================================================
#define CSTG_W (2 * 128 * CWP)
#define COFF_A 0
#define COFF_B (128 * CWP)
#define CV_SMEM (128 * ZP2 * 4)   // 66048 >= 2*CSTG_W*4 = 40960

__global__ __launch_bounds__(256) void conv_gemm_kernel(const int* __restrict__ llen,
                                                        const int* __restrict__ rlen,
                                                        const float* __restrict__ cb1,
                                                        const float* __restrict__ cb2,
                                                        const float* __restrict__ cb3) {
    extern __shared__ unsigned smw[];
    int zb = blockIdx.z;
    int side = zb >> 9, b = zb & 511;
    int mt = blockIdx.x;               // 0: rows 0..127, 1: rows 96..159(+pad)
    int tileN = blockIdx.y;            // 0..4
    int len = side ? rlen[b] : llen[b];
    if (mt == 1 && len < 127) return;
    int m0 = mt * 96;
    int n0 = tileN * 128;

    const unsigned* Ax = (side ? g_rcx : g_lcx) + (size_t)b * LSZ * DPW;

    int tid  = threadIdx.x;
    int lane = tid & 31;
    int wid  = tid >> 5;
    int wm   = wid & 3;
    int wn   = wid >> 2;

    unsigned sbase = (unsigned)__cvta_generic_to_shared(smw);

    float acc[2][8][4];
#pragma unroll
    for (int ms = 0; ms < 2; ms++)
#pragma unroll
        for (int nf = 0; nf < 8; nf++)
#pragma unroll
            for (int q = 0; q < 4; q++) acc[ms][nf][q] = 0.f;

#define CCOPY(kb, s) do {                                                         \
    unsigned sb0 = sbase + (s) * (CSTG_W * 4);                                    \
    _Pragma("unroll")                                                             \
    for (int q = 0; q < 2; q++) {                                                 \
        int cid = tid + 256 * q;                                                  \
        int r = cid >> 2, c = cid & 3;                                            \
        bool aok = (m0 + r) < LSZ;                                                \
        cp16(sb0 + (COFF_A + r * CWP + c * 4) * 4,                                \
             Ax + (size_t)(aok ? m0 + r : 0) * DPW + (kb) * 16 + c * 4, aok);     \
        cp16(sb0 + (COFF_B + r * CWP + c * 4) * 4,                                \
             g_wallh + (size_t)(n0 + r) * DPW + (kb) * 16 + c * 4, true);         \
    }                                                                             \
} while (0)

    CCOPY(0, 0);
    cpcommit();

    for (int kb = 0; kb < NKB; kb++) {
        cpwait<0>();
        __syncthreads();
        if (kb + 1 < NKB) {
            CCOPY(kb + 1, (kb + 1) & 1);
            cpcommit();
        }

        unsigned sb0 = sbase + (kb & 1) * (CSTG_W * 4);
#pragma unroll
        for (int ks = 0; ks < 2; ks++) {
            unsigned af[2][4];
#pragma unroll
            for (int ms = 0; ms < 2; ms++) {
                int r = wm * 32 + ms * 16 + (lane & 7) + ((lane >> 3) & 1) * 8;
                int c = ks * 2 + (lane >> 4);
                ldx4(af[ms], sb0 + (COFF_A + r * CWP + c * 4) * 4);
            }
#pragma unroll
            for (int nfp = 0; nfp < 4; nfp++) {
                int rB = wn * 64 + nfp * 16 + ((lane >> 4) & 1) * 8 + (lane & 7);
                int cB = ks * 2 + ((lane >> 3) & 1);
                unsigned bf[4];
                ldx4(bf, sb0 + (COFF_B + rB * CWP + cB * 4) * 4);
#pragma unroll
                for (int ms = 0; ms < 2; ms++) {
                    mma16h(acc[ms][2 * nfp],     af[ms], bf[0], bf[1]);
                    mma16h(acc[ms][2 * nfp + 1], af[ms], bf[2], bf[3]);
                }
            }
        }
    }
#undef CCOPY

    __syncthreads();   // all warps done with stage buffers before Z-alias writes

    float* Zs = (float*)smw;
#pragma unroll
    for (int ms = 0; ms < 2; ms++) {
        int r = wm * 32 + ms * 16 + (lane >> 2);
#pragma unroll
        for (int nf = 0; nf < 8; nf++) {
            int jc = wn * 64 + nf * 8 + 2 * (lane & 3);
            Zs[r * ZP2 + jc]           = acc[ms][nf][0];
            Zs[r * ZP2 + jc + 1]       = acc[ms][nf][1];
            Zs[(r + 8) * ZP2 + jc]     = acc[ms][nf][2];
            Zs[(r + 8) * ZP2 + jc + 1] = acc[ms][nf][3];
        }
    }
    __syncthreads();

    if (tid < 60) {
        int o_l = tid / 3, cv = tid % 3;
        int o_g = tileN * 20 + o_l;
        if (o_g < 100) {
            int cb = o_l * 6;
            float bias = (cv == 0) ? cb1[o_g] : (cv == 1 ? cb2[o_g] : cb3[o_g]);
            int k = cv + 1;
            int lo = (mt == 0) ? 0 : 126;
            int hi = min(len - k, (mt == 0) ? 125 : 159);
            if (hi >= lo) {
                float mx = 0.f;
                if (cv == 0) {
                    for (int t = lo; t <= hi; t++) {
                        int tl = t - m0;
                        mx = fmaxf(mx, Zs[tl * ZP2 + cb] + bias);
                    }
                } else if (cv == 1) {
                    for (int t = lo; t <= hi; t++) {
                        int tl = t - m0;
                        mx = fmaxf(mx, Zs[tl * ZP2 + cb + 1] + Zs[(tl + 1) * ZP2 + cb + 2] + bias);
                    }
                } else {
                    for (int t = lo; t <= hi; t++) {
                        int tl = t - m0;
                        mx = fmaxf(mx, Zs[tl * ZP2 + cb + 3] + Zs[(tl + 1) * ZP2 + cb + 4]
                                     + Zs[(tl + 2) * ZP2 + cb + 5] + bias);
                    }
                }
                int fidx = b * NCH + side * 300 + cv * 100 + o_g;
                atomicMax((int*)&g_feats[fidx], __float_as_int(mx));
            }
        }
    }
}

// ---------------- dense head ----------------
__global__ void dense_kernel(const float* __restrict__ dw1, const float* __restrict__ db1,
                             const float* __restrict__ dw2, const float* __restrict__ db2,
                             float* __restrict__ out) {
    int b = blockIdx.x;
    __shared__ float f[NCH];
    __shared__ float h[64];
    int tid = threadIdx.x;
    for (int j = tid; j < NCH; j += blockDim.x) f[j] = g_feats[(size_t)b * NCH + j];
    __syncthreads();
    if (tid < 60) {
        float s = db1[tid];
        for (int j = 0; j < NCH; j++) s += f[j] * dw1[j * 60 + tid];
        h[tid] = fmaxf(s, 0.f);
    }
    __syncthreads();
    if (tid < 2) {
        float s = db2[tid];
        for (int j = 0; j < 60; j++) s += h[j] * dw2[j * 2 + tid];
        out[b * 2 + tid] = s;
    }
}

// ---------------- launch ----------------
extern "C" void kernel_launch(void* const* d_in, const int* in_sizes, int n_in,
                              void* d_out, int out_size) {
    const int*   lt   = (const int*)d_in[0];
    const int*   la   = (const int*)d_in[1];
    const int*   ll   = (const int*)d_in[2];
    const int*   rt   = (const int*)d_in[3];
    const int*   ra   = (const int*)d_in[4];
    const int*   rl   = (const int*)d_in[5];
    const float* wemb = (const float*)d_in[6];
    const float* aemb = (const float*)d_in[7];
    const float* cw1  = (const float*)d_in[8];
    const float* cb1  = (const float*)d_in[9];
    const float* cw2  = (const float*)d_in[10];
    const float* cb2  = (const float*)d_in[11];
    const float* cw3  = (const float*)d_in[12];
    const float* cb3  = (const float*)d_in[13];
    const float* dw1  = (const float*)d_in[14];
    const float* db1  = (const float*)d_in[15];
    const float* dw2  = (const float*)d_in[16];
    const float* db2  = (const float*)d_in[17];
    float* out = (float*)d_out;

    const int attSmem = AST_W * 4 * 2;   // 40960 bytes
    cudaFuncSetAttribute(conv_gemm_kernel,
                         cudaFuncAttributeMaxDynamicSharedMemorySize, CV_SMEM);
    cudaFuncSetAttribute(att_gemm_kernel,
                         cudaFuncAttributeMaxDynamicSharedMemorySize, attSmem);

    init_kernel<<<(BSZ * NCH + 255) / 256, 256>>>(cw1, cw2, cw3);
    gather_kernel<<<dim3(LSZ / 4, BSZ, 2), 192>>>(lt, la, rt, ra, wemb, aemb, ll, rl);
    att_gemm_kernel<<<dim3(3, 3, BSZ), 256, attSmem>>>(ll, rl);
    attproc_kernel<<<dim3((BSZ * LSZ) / 4, 2), 128>>>(ll, rl);
    conv_gemm_kernel<<<dim3(2, 5, 2 * BSZ), 256, CV_SMEM>>>(ll, rl, cb1, cb2, cb3);
    dense_kernel<<<BSZ, 128>>>(dw1, db1, dw2, db2, out);
}